// round 2
// baseline (speedup 1.0000x reference)
#include <cuda_runtime.h>
#include <cuda_bf16.h>
#include <math.h>
#include <stdint.h>

// Problem constants
#define Bq   2
#define Tq   2048
#define Cq   1024
#define Hq   16
#define HSq  64
#define FFq  4096
#define BTq  (Bq*Tq)          // 4096
#define EPSq 1e-5f

typedef long long ll;

// ---------------------------------------------------------------------------
// Scratch (device globals — allocation-free)
// ---------------------------------------------------------------------------
__device__ float g_h  [(size_t)BTq*Cq];
__device__ float g_q  [(size_t)Hq*BTq*HSq];           // [H][B*T][HS]
__device__ float g_k  [(size_t)Hq*BTq*HSq];
__device__ float g_v  [(size_t)Hq*BTq*HSq];
__device__ float g_S  [(size_t)Bq*Hq*Tq*Tq];          // z = h*B + b
__device__ float g_att[(size_t)BTq*Cq];
__device__ float g_x1 [(size_t)BTq*Cq];
__device__ float g_ff [(size_t)BTq*FFq];

// ---------------------------------------------------------------------------
// Helpers
// ---------------------------------------------------------------------------
__device__ __forceinline__ float cvtf32(float f) {
    uint32_t u;
    asm("cvt.rna.tf32.f32 %0, %1;" : "=r"(u) : "f"(f));
    return __uint_as_float(u);
}

__device__ __forceinline__ void mma_tf32(float* c, const uint32_t* a, const uint32_t* b) {
    asm volatile(
        "mma.sync.aligned.m16n8k8.row.col.f32.tf32.tf32.f32 "
        "{%0,%1,%2,%3},{%4,%5,%6,%7},{%8,%9},{%0,%1,%2,%3};"
        : "+f"(c[0]), "+f"(c[1]), "+f"(c[2]), "+f"(c[3])
        : "r"(a[0]), "r"(a[1]), "r"(a[2]), "r"(a[3]), "r"(b[0]), "r"(b[1]));
}

// ---------------------------------------------------------------------------
// LayerNorm: one block per row, 256 threads, float4
// ---------------------------------------------------------------------------
__global__ __launch_bounds__(256)
void layernorm_kernel(const float* __restrict__ x, const float* __restrict__ w,
                      float* __restrict__ out)
{
    ll r = blockIdx.x;
    int t = threadIdx.x;
    const float4* xr = reinterpret_cast<const float4*>(x + r * Cq);
    float4 v = xr[t];
    float sum = v.x + v.y + v.z + v.w;
    float sq  = v.x*v.x + v.y*v.y + v.z*v.z + v.w*v.w;
    #pragma unroll
    for (int o = 16; o; o >>= 1) {
        sum += __shfl_xor_sync(0xffffffffu, sum, o);
        sq  += __shfl_xor_sync(0xffffffffu, sq,  o);
    }
    __shared__ float s1[8], s2[8];
    __shared__ float mu_s, rstd_s;
    int wid = t >> 5, lane = t & 31;
    if (lane == 0) { s1[wid] = sum; s2[wid] = sq; }
    __syncthreads();
    if (t == 0) {
        float S = 0.f, Q = 0.f;
        #pragma unroll
        for (int i = 0; i < 8; i++) { S += s1[i]; Q += s2[i]; }
        float mu  = S * (1.0f / Cq);
        float var = Q * (1.0f / Cq) - mu * mu;
        mu_s = mu;
        rstd_s = rsqrtf(var + EPSq);
    }
    __syncthreads();
    float mu = mu_s, rstd = rstd_s;
    float4 ww = reinterpret_cast<const float4*>(w)[t];
    float4 o;
    o.x = (v.x - mu) * rstd * ww.x;
    o.y = (v.y - mu) * rstd * ww.y;
    o.z = (v.z - mu) * rstd * ww.z;
    o.w = (v.w - mu) * rstd * ww.w;
    reinterpret_cast<float4*>(out + r * Cq)[t] = o;
}

// ---------------------------------------------------------------------------
// tf32 tensor-core GEMM.  C[z] = alpha * A[z] @ B[z] (+bias)(+relu)(+res)(mask)
// A row-major [M][lda] (k contiguous).
// B: BTRANS=false -> [K][ldb] (n contig);  BTRANS=true -> [N][ldb] (k contig).
// BM = 128 fixed, BK = 16, 256 threads (8 warps: 4 along M x 2 along N).
// Fragment-shuffled SMEM: compute phase does conflict-free LDS.128 / LDS.64.
// CAUSAL_K: Keff = min(K, m0+128).  MASK: scores (-inf above diag, skip tiles
// fully above diagonal).
// ---------------------------------------------------------------------------
template<int BN, bool BTRANS, bool BIAS, bool RELU, bool RES, bool CAUSAL_K, bool MASK>
__global__ __launch_bounds__(256)
void tf32gemm(const float* __restrict__ A, ll sA1, ll sA2,
              const float* __restrict__ Bm, ll sB1, ll sB2,
              const float* __restrict__ bias, ll sb1, ll sb2,
              const float* __restrict__ res,  ll sr1, ll sr2,
              float* __restrict__ C, ll sC1, ll sC2,
              int Z2, int K, int lda, int ldb, int ldc, float alpha)
{
    constexpr int BM   = 128;
    constexpr int MT   = BM / 16;        // 8 m-tiles
    constexpr int NT   = BN / 8;         // n-tiles
    constexpr int NTPW = NT / 2;         // n-tiles per warp
    constexpr int WN   = BN / 2;         // n-extent per warp
    constexpr int NBV  = BN / 64;        // B-loader float4s per thread

    const int tid  = threadIdx.x;
    const int lane = tid & 31;
    const int wid  = tid >> 5;
    const int warpM = wid & 3;
    const int warpN = wid >> 2;

    const int z  = blockIdx.z;
    const int z1 = z / Z2, z2 = z - z1 * Z2;
    const int m0 = blockIdx.y * BM;
    const int n0 = blockIdx.x * BN;

    if (MASK && n0 > m0) return;     // tile fully above causal diagonal

    const float* Ap = A  + z1 * sA1 + z2 * sA2;
    const float* Bp = Bm + z1 * sB1 + z2 * sB2;
    float*       Cp = C  + z1 * sC1 + z2 * sC2;
    const float* biasp = BIAS ? (bias + z1 * sb1 + z2 * sb2) : nullptr;
    const float* resp  = RES  ? (res  + z1 * sr1 + z2 * sr2) : nullptr;

    const int Keff = CAUSAL_K ? min(K, m0 + BM) : K;
    const int nk = Keff >> 4;

    __shared__ float Asf[2][2][MT][32][4];
    __shared__ float Bsf[2][2][NT][32][2];

    // ---- A loader mapping (float4 along k) ----
    const int a_row = tid >> 2;          // 0..63
    const int a_kq  = tid & 3;           // float4 index in BK
    const int a_r     = a_row & 15;
    const int a_lane0 = (a_r & 7) * 4;
    const int a_reg   = (a_r >> 3) + 2 * (a_kq & 1);
    const int a_ks    = a_kq >> 1;
    const int a_mt0   = a_row >> 4;      // mtile for pass 0 (pass1 = +4)
    const float* a_base = Ap + (ll)(m0 + a_row) * lda + a_kq * 4;

    // ---- B loader mapping ----
    // n-contig variant
    const int bn_n  = (tid % (BN / 4)) * 4;
    const int bn_k0 = tid / (BN / 4);                  // row in pass 0
    const int BRPP  = 256 / (BN / 4);                  // rows per pass
    // k-contig (trans) variant
    const int bt_row = tid >> 2;
    const int bt_kq  = tid & 3;

    float4 av[2];
    float4 bv[NBV];

    float acc[2][NTPW][4];
    #pragma unroll
    for (int i = 0; i < 2; i++)
        #pragma unroll
        for (int j = 0; j < NTPW; j++)
            #pragma unroll
            for (int r = 0; r < 4; r++) acc[i][j][r] = 0.f;

    // ---------------- device lambdas as macros ----------------
    #define LDG_TILE(k0)                                                        \
    {                                                                           \
        av[0] = *reinterpret_cast<const float4*>(a_base + (k0));                \
        av[1] = *reinterpret_cast<const float4*>(a_base + (k0) + 64 * (ll)lda); \
        if (BTRANS) {                                                           \
            _Pragma("unroll")                                                   \
            for (int p = 0; p < NBV; p++)                                       \
                bv[p] = *reinterpret_cast<const float4*>(                       \
                    Bp + (ll)(n0 + bt_row + p * 64) * ldb + (k0) + bt_kq * 4);  \
        } else {                                                                \
            _Pragma("unroll")                                                   \
            for (int p = 0; p < NBV; p++)                                       \
                bv[p] = *reinterpret_cast<const float4*>(                       \
                    Bp + (ll)((k0) + bn_k0 + p * BRPP) * ldb + n0 + bn_n);      \
        }                                                                       \
    }

    #define STS_TILE(buf)                                                       \
    {                                                                           \
        _Pragma("unroll")                                                       \
        for (int p = 0; p < 2; p++) {                                           \
            float* d = &Asf[buf][a_ks][a_mt0 + p * 4][a_lane0][a_reg];          \
            d[0]  = cvtf32(av[p].x);                                            \
            d[4]  = cvtf32(av[p].y);                                            \
            d[8]  = cvtf32(av[p].z);                                            \
            d[12] = cvtf32(av[p].w);                                            \
        }                                                                       \
        if (BTRANS) {                                                           \
            _Pragma("unroll")                                                   \
            for (int p = 0; p < NBV; p++) {                                     \
                int n = bt_row + p * 64;                                        \
                float* d = &Bsf[buf][bt_kq >> 1][n >> 3][(n & 7) * 4][bt_kq & 1];\
                d[0] = cvtf32(bv[p].x);                                         \
                d[2] = cvtf32(bv[p].y);                                         \
                d[4] = cvtf32(bv[p].z);                                         \
                d[6] = cvtf32(bv[p].w);                                         \
            }                                                                   \
        } else {                                                                \
            _Pragma("unroll")                                                   \
            for (int p = 0; p < NBV; p++) {                                     \
                int kk = bn_k0 + p * BRPP;                                      \
                float* d = &Bsf[buf][kk >> 3][bn_n >> 3]                        \
                               [(bn_n & 7) * 4 + (kk & 3)][(kk & 7) >> 2];      \
                d[0]  = cvtf32(bv[p].x);                                        \
                d[8]  = cvtf32(bv[p].y);                                        \
                d[16] = cvtf32(bv[p].z);                                        \
                d[24] = cvtf32(bv[p].w);                                        \
            }                                                                   \
        }                                                                       \
    }

    #define COMPUTE(buf)                                                        \
    {                                                                           \
        _Pragma("unroll")                                                       \
        for (int ks = 0; ks < 2; ks++) {                                        \
            uint32_t af[2][4];                                                  \
            uint32_t bf[NTPW][2];                                               \
            _Pragma("unroll")                                                   \
            for (int mt2 = 0; mt2 < 2; mt2++)                                   \
                *reinterpret_cast<uint4*>(af[mt2]) =                            \
                    *reinterpret_cast<const uint4*>(                            \
                        &Asf[buf][ks][warpM * 2 + mt2][lane][0]);               \
            _Pragma("unroll")                                                   \
            for (int nt2 = 0; nt2 < NTPW; nt2++)                                \
                *reinterpret_cast<uint2*>(bf[nt2]) =                            \
                    *reinterpret_cast<const uint2*>(                            \
                        &Bsf[buf][ks][warpN * NTPW + nt2][lane][0]);            \
            _Pragma("unroll")                                                   \
            for (int mt2 = 0; mt2 < 2; mt2++)                                   \
                _Pragma("unroll")                                               \
                for (int nt2 = 0; nt2 < NTPW; nt2++)                            \
                    mma_tf32(acc[mt2][nt2], af[mt2], bf[nt2]);                  \
        }                                                                       \
    }
    // -----------------------------------------------------------

    LDG_TILE(0);
    STS_TILE(0);
    __syncthreads();

    for (int t = 0; t < nk; t++) {
        int buf = t & 1;
        bool has = (t + 1 < nk);
        if (has) { int k0 = (t + 1) << 4; LDG_TILE(k0); }
        COMPUTE(buf);
        if (has) {
            STS_TILE(buf ^ 1);
            __syncthreads();
        }
    }

    // ---- epilogue ----
    #pragma unroll
    for (int mt2 = 0; mt2 < 2; mt2++) {
        int row0 = m0 + warpM * 32 + mt2 * 16 + (lane >> 2);
        #pragma unroll
        for (int nt2 = 0; nt2 < NTPW; nt2++) {
            int col = n0 + warpN * WN + nt2 * 8 + (lane & 3) * 2;
            float b0 = 0.f, b1 = 0.f;
            if (BIAS) {
                float2 bb = *reinterpret_cast<const float2*>(biasp + col);
                b0 = bb.x; b1 = bb.y;
            }
            #pragma unroll
            for (int rr = 0; rr < 2; rr++) {
                int row = row0 + rr * 8;
                float v0 = acc[mt2][nt2][rr * 2 + 0] * alpha + b0;
                float v1 = acc[mt2][nt2][rr * 2 + 1] * alpha + b1;
                if (RELU) { v0 = fmaxf(v0, 0.f); v1 = fmaxf(v1, 0.f); }
                if (RES) {
                    float2 rv = *reinterpret_cast<const float2*>(
                        resp + (ll)row * ldc + col);
                    v0 += rv.x; v1 += rv.y;
                }
                if (MASK) {
                    if (col     > row) v0 = -INFINITY;
                    if (col + 1 > row) v1 = -INFINITY;
                }
                *reinterpret_cast<float2*>(Cp + (ll)row * ldc + col) =
                    make_float2(v0, v1);
            }
        }
    }
    #undef LDG_TILE
    #undef STS_TILE
    #undef COMPUTE
}

// ---------------------------------------------------------------------------
// Column softmax (query-axis), coalesced: block = 256 consecutive columns,
// row-major sweep.  Guard i>=j ensures skipped (never-written) tiles above the
// diagonal are never consumed -> deterministic across graph replays.
// ---------------------------------------------------------------------------
__global__ __launch_bounds__(256)
void softmax_col_kernel(float* __restrict__ S)
{
    const int z  = blockIdx.y;
    const int j0 = blockIdx.x * 256;
    const int j  = j0 + threadIdx.x;
    float* Sz = S + (ll)z * Tq * Tq;

    float m = -INFINITY, s = 0.f;
    for (int i = j0; i < Tq; i++) {
        float v = Sz[(ll)i * Tq + j];
        if (i >= j) {
            if (v > m) { s = s * __expf(m - v) + 1.f; m = v; }
            else       { s += __expf(v - m); }
        }
    }
    float inv = 1.0f / s;
    int i0 = (j >> 7) << 7;           // align to the 128-row GEMM band
    for (int i = i0; i < Tq; i++) {
        ll idx = (ll)i * Tq + j;
        Sz[idx] = __expf(Sz[idx] - m) * inv;   // -inf -> 0 above diagonal
    }
}

// ---------------------------------------------------------------------------
// Launch sequence
// ---------------------------------------------------------------------------
extern "C" void kernel_launch(void* const* d_in, const int* in_sizes, int n_in,
                              void* d_out, int out_size)
{
    const float* x     = (const float*)d_in[0];
    const float* ln1_w = (const float*)d_in[1];
    const float* Wq    = (const float*)d_in[2];
    const float* bq    = (const float*)d_in[3];
    const float* Wk    = (const float*)d_in[4];
    const float* bk    = (const float*)d_in[5];
    const float* Wv    = (const float*)d_in[6];
    const float* bv    = (const float*)d_in[7];
    const float* Wo    = (const float*)d_in[8];
    const float* bo    = (const float*)d_in[9];
    const float* ln2_w = (const float*)d_in[10];
    const float* W1    = (const float*)d_in[11];
    const float* b1    = (const float*)d_in[12];
    const float* W2    = (const float*)d_in[13];
    const float* b2    = (const float*)d_in[14];
    float* out = (float*)d_out;

    void *ph_, *pq_, *pk_, *pv_, *pS_, *patt_, *px1_, *pff_;
    cudaGetSymbolAddress(&ph_,  g_h);
    cudaGetSymbolAddress(&pq_,  g_q);
    cudaGetSymbolAddress(&pk_,  g_k);
    cudaGetSymbolAddress(&pv_,  g_v);
    cudaGetSymbolAddress(&pS_,  g_S);
    cudaGetSymbolAddress(&patt_, g_att);
    cudaGetSymbolAddress(&px1_, g_x1);
    cudaGetSymbolAddress(&pff_, g_ff);
    float* ph   = (float*)ph_;
    float* pq   = (float*)pq_;
    float* pk   = (float*)pk_;
    float* pv   = (float*)pv_;
    float* pS   = (float*)pS_;
    float* patt = (float*)patt_;
    float* px1  = (float*)px1_;
    float* pff  = (float*)pff_;

    // 1) LN1
    layernorm_kernel<<<BTq, 256>>>(x, ln1_w, ph);

    // 2) QKV: per-head [BT,1024]@[1024,64] + bias, z = head
    {
        dim3 grid(1, BTq / 128, Hq);
        ll sW = (ll)Cq * HSq, sC = (ll)BTq * HSq;
        tf32gemm<64,false,true,false,false,false,false><<<grid, 256>>>(
            ph, 0, 0, Wq, sW, 0, bq, HSq, 0, nullptr, 0, 0, pq, sC, 0,
            1, Cq, Cq, HSq, HSq, 1.0f);
        tf32gemm<64,false,true,false,false,false,false><<<grid, 256>>>(
            ph, 0, 0, Wk, sW, 0, bk, HSq, 0, nullptr, 0, 0, pk, sC, 0,
            1, Cq, Cq, HSq, HSq, 1.0f);
        tf32gemm<64,false,true,false,false,false,false><<<grid, 256>>>(
            ph, 0, 0, Wv, sW, 0, bv, HSq, 0, nullptr, 0, 0, pv, sC, 0,
            1, Cq, Cq, HSq, HSq, 1.0f);
    }

    // 3) Scores: S = (Q K^T) * HS^-0.5, causal mask, z = h*B+b
    {
        dim3 grid(Tq / 128, Tq / 128, Hq * Bq);
        tf32gemm<128,true,false,false,false,false,true><<<grid, 256>>>(
            pq, (ll)Tq * HSq, 0, pk, (ll)Tq * HSq, 0,
            nullptr, 0, 0, nullptr, 0, 0, pS, (ll)Tq * Tq, 0,
            1, HSq, HSq, HSq, Tq, 0.125f);
    }

    // 4) Column softmax (query axis)
    {
        dim3 grid(Tq / 256, Hq * Bq);
        softmax_col_kernel<<<grid, 256>>>(pS);
    }

    // 5) att = W @ V (causal-K), scatter into [B*T][H*HS]; z1=h, z2=b
    {
        dim3 grid(1, Tq / 128, Hq * Bq);
        tf32gemm<64,false,false,false,false,true,false><<<grid, 256>>>(
            pS, (ll)Bq * Tq * Tq, (ll)Tq * Tq,
            pv, (ll)Bq * Tq * HSq, (ll)Tq * HSq,
            nullptr, 0, 0, nullptr, 0, 0,
            patt, (ll)HSq, (ll)Tq * Cq,
            Bq, Tq, Tq, HSq, Cq, 1.0f);
    }

    // 6) x1 = x + att @ Wo + bo
    {
        dim3 grid(Cq / 128, BTq / 128, 1);
        tf32gemm<128,false,true,false,true,false,false><<<grid, 256>>>(
            patt, 0, 0, Wo, 0, 0, bo, 0, 0, x, 0, 0, px1, 0, 0,
            1, Cq, Cq, Cq, Cq, 1.0f);
    }

    // 7) LN2
    layernorm_kernel<<<BTq, 256>>>(px1, ln2_w, ph);

    // 8) FF1: relu(h2 @ W1 + b1)
    {
        dim3 grid(FFq / 128, BTq / 128, 1);
        tf32gemm<128,false,true,true,false,false,false><<<grid, 256>>>(
            ph, 0, 0, W1, 0, 0, b1, 0, 0, nullptr, 0, 0, pff, 0, 0,
            1, Cq, Cq, FFq, FFq, 1.0f);
    }

    // 9) out = x1 + ff @ W2 + b2
    {
        dim3 grid(Cq / 128, BTq / 128, 1);
        tf32gemm<128,false,true,false,true,false,false><<<grid, 256>>>(
            pff, 0, 0, W2, 0, 0, b2, 0, 0, px1, 0, 0, out, 0, 0,
            1, FFq, FFq, Cq, Cq, 1.0f);
    }
}

// round 4
// speedup vs baseline: 1.7231x; 1.7231x over previous
#include <cuda_runtime.h>
#include <cuda_bf16.h>
#include <math.h>
#include <stdint.h>

#define Bq   2
#define Tq   2048
#define Cq   1024
#define Hq   16
#define HSq  64
#define FFq  4096
#define BTq  (Bq*Tq)          // 4096
#define EPSq 1e-5f

typedef long long ll;

// ---------------------------------------------------------------------------
// Scratch (device globals — allocation-free)
// ---------------------------------------------------------------------------
__device__ float g_h  [(size_t)BTq*Cq];
__device__ float g_q  [(size_t)BTq*Cq];               // [B*T][H*HS]
__device__ float g_k  [(size_t)BTq*Cq];
__device__ float g_vt [(size_t)Cq*BTq];               // [H*HS][B*T]
__device__ float g_S  [(size_t)Hq*Bq*Tq*Tq];          // [H][B][T][T]
__device__ float g_att[(size_t)BTq*Cq];
__device__ float g_x1 [(size_t)BTq*Cq];
__device__ float g_ff [(size_t)BTq*FFq];
__device__ float g_wqt[(size_t)Cq*Cq];                // [H*HS][C]
__device__ float g_wkt[(size_t)Cq*Cq];
__device__ float g_wvt[(size_t)Cq*Cq];
__device__ float g_wot[(size_t)Cq*Cq];                // [C][H*HS]
__device__ float g_w1t[(size_t)FFq*Cq];               // [FF][C]
__device__ float g_w2t[(size_t)Cq*FFq];               // [C][FF]

// ---------------------------------------------------------------------------
// helpers
// ---------------------------------------------------------------------------
__device__ __forceinline__ float cvtf32(float f) {
    uint32_t u;
    asm("cvt.rna.tf32.f32 %0, %1;" : "=r"(u) : "f"(f));
    return __uint_as_float(u);
}
__device__ __forceinline__ uint32_t smem_u32(const void* p) {
    uint32_t a;
    asm("{ .reg .u64 t; cvta.to.shared.u64 t, %1; cvt.u32.u64 %0, t; }"
        : "=r"(a) : "l"(p));
    return a;
}
__device__ __forceinline__ void cpasync16(uint32_t dst, const void* src) {
    asm volatile("cp.async.cg.shared.global [%0], [%1], 16;"
                 :: "r"(dst), "l"(src));
}
#define CP_COMMIT() asm volatile("cp.async.commit_group;" ::: "memory")
#define CP_WAIT1()  asm volatile("cp.async.wait_group 1;" ::: "memory")

__device__ __forceinline__ void ldsm4(uint32_t* r, uint32_t a) {
    asm volatile("ldmatrix.sync.aligned.m8n8.x4.shared.b16 {%0,%1,%2,%3}, [%4];"
        : "=r"(r[0]), "=r"(r[1]), "=r"(r[2]), "=r"(r[3]) : "r"(a));
}
__device__ __forceinline__ void mma_tf32(float* c, const uint32_t* a, const uint32_t* b) {
    asm volatile(
        "mma.sync.aligned.m16n8k8.row.col.f32.tf32.tf32.f32 "
        "{%0,%1,%2,%3},{%4,%5,%6,%7},{%8,%9},{%0,%1,%2,%3};"
        : "+f"(c[0]), "+f"(c[1]), "+f"(c[2]), "+f"(c[3])
        : "r"(a[0]), "r"(a[1]), "r"(a[2]), "r"(a[3]), "r"(b[0]), "r"(b[1]));
}

// ---------------------------------------------------------------------------
// LayerNorm (tf32-rounds its output: consumed only as GEMM operand)
// ---------------------------------------------------------------------------
__global__ __launch_bounds__(256)
void layernorm_kernel(const float* __restrict__ x, const float* __restrict__ w,
                      float* __restrict__ out)
{
    ll r = blockIdx.x;
    int t = threadIdx.x;
    const float4* xr = reinterpret_cast<const float4*>(x + r * Cq);
    float4 v = xr[t];
    float sum = v.x + v.y + v.z + v.w;
    float sq  = v.x*v.x + v.y*v.y + v.z*v.z + v.w*v.w;
    #pragma unroll
    for (int o = 16; o; o >>= 1) {
        sum += __shfl_xor_sync(0xffffffffu, sum, o);
        sq  += __shfl_xor_sync(0xffffffffu, sq,  o);
    }
    __shared__ float s1[8], s2[8];
    __shared__ float mu_s, rstd_s;
    int wid = t >> 5, lane = t & 31;
    if (lane == 0) { s1[wid] = sum; s2[wid] = sq; }
    __syncthreads();
    if (t == 0) {
        float S = 0.f, Q = 0.f;
        #pragma unroll
        for (int i = 0; i < 8; i++) { S += s1[i]; Q += s2[i]; }
        float mu  = S * (1.0f / Cq);
        float var = Q * (1.0f / Cq) - mu * mu;
        mu_s = mu; rstd_s = rsqrtf(var + EPSq);
    }
    __syncthreads();
    float mu = mu_s, rstd = rstd_s;
    float4 ww = reinterpret_cast<const float4*>(w)[t];
    float4 o;
    o.x = cvtf32((v.x - mu) * rstd * ww.x);
    o.y = cvtf32((v.y - mu) * rstd * ww.y);
    o.z = cvtf32((v.z - mu) * rstd * ww.z);
    o.w = cvtf32((v.w - mu) * rstd * ww.w);
    reinterpret_cast<float4*>(out + r * Cq)[t] = o;
}

// ---------------------------------------------------------------------------
// Batched transpose (tf32-rounds output)
// ---------------------------------------------------------------------------
__global__ __launch_bounds__(256)
void transpose_kernel(const float* __restrict__ src, ll s_src,
                      float* __restrict__ dst, ll s_dst,
                      int lds, int ldd)
{
    __shared__ float tile[32][33];
    const float* sp = src + (ll)blockIdx.z * s_src;
    float*       dp = dst + (ll)blockIdx.z * s_dst;
    int cc0 = blockIdx.x * 32;
    int r0  = blockIdx.y * 32;
    int tx = threadIdx.x & 31, ty = threadIdx.x >> 5;
    #pragma unroll
    for (int p = 0; p < 4; p++)
        tile[ty + p * 8][tx] = sp[(ll)(r0 + ty + p * 8) * lds + cc0 + tx];
    __syncthreads();
    #pragma unroll
    for (int p = 0; p < 4; p++)
        dp[(ll)(cc0 + ty + p * 8) * ldd + r0 + tx] = cvtf32(tile[tx][ty + p * 8]);
}

// ---------------------------------------------------------------------------
// mma.sync tf32 GEMM, cp.async 3-stage + ldmatrix.
// C = alpha*A@B^T (+bias)(+relu)(+res)(mask)(ctrans)(cvt)
// A [M][lda] k-contig; B [N][ldb] k-contig.  BM=128, BK=16, 256 thr (4x2 warps)
// ---------------------------------------------------------------------------
template<int BN, bool BIAS, bool RELU, bool RES, bool CAUSAL_K, bool MASK,
         bool CTRANS, bool CVT>
__global__ __launch_bounds__(256)
void mma_gemm(const float* __restrict__ A, ll sA1, ll sA2,
              const float* __restrict__ Bm, ll sB1, ll sB2,
              const float* __restrict__ bias,
              const float* __restrict__ res,
              float* __restrict__ C, ll sC1, ll sC2,
              int Z2, int K, int lda, int ldb, int ldc, float alpha)
{
    constexpr int BM   = 128;
    constexpr int ROWB = 80;                     // padded row bytes (16 floats + 4)
    constexpr int A_TILE = BM * ROWB;            // 10240
    constexpr int B_TILE = BN * ROWB;
    constexpr int STAGE  = A_TILE + B_TILE;
    constexpr int NTPW = BN / 16;                // n8-tiles per warp
    constexpr int NGRP = NTPW / 2;               // ldmatrix.x4 groups
    constexpr int WN   = BN / 2;

    extern __shared__ __align__(16) char dsm[];
    const uint32_t sb = smem_u32(dsm);

    const int tid  = threadIdx.x;
    const int lane = tid & 31;
    const int wid  = tid >> 5;
    const int warpM = wid & 3;
    const int warpN = wid >> 2;

    const int z  = blockIdx.z;
    const int z1 = z / Z2, z2 = z - z1 * Z2;
    const int m0 = blockIdx.y * BM;
    const int n0 = blockIdx.x * BN;
    if (MASK && n0 > m0) return;

    const float* Ap = A  + z1 * sA1 + z2 * sA2;
    const float* Bp = Bm + z1 * sB1 + z2 * sB2;
    float*       Cp = C  + z1 * sC1 + z2 * sC2;

    const int Keff = CAUSAL_K ? min(K, m0 + BM) : K;
    const int nk = Keff >> 4;

    // loader mapping: thread -> (row = tid>>2 [+64], float4 col = tid&3)
    const int lr = tid >> 2;
    const int lk = tid & 3;
    const float* a_g = Ap + (ll)(m0 + lr) * lda + lk * 4;
    const float* b_g = Bp + (ll)(n0 + lr) * ldb + lk * 4;
    const uint32_t a_off = (uint32_t)(lr * ROWB + lk * 16);
    const uint32_t b_off = a_off;

    #define ISSUE(t)                                                          \
    {                                                                         \
        int k0 = (t) << 4;                                                    \
        uint32_t as = sb + ((t) % 3) * STAGE;                                 \
        uint32_t bs = as + A_TILE;                                            \
        cpasync16(as + a_off, a_g + k0);                                      \
        cpasync16(as + a_off + 64 * ROWB, a_g + k0 + 64 * (ll)lda);           \
        cpasync16(bs + b_off, b_g + k0);                                      \
        if (BN == 128)                                                        \
            cpasync16(bs + b_off + 64 * ROWB, b_g + k0 + 64 * (ll)ldb);       \
    }

    // ldmatrix lane addressing
    const uint32_t a_lmoff =
        (uint32_t)((warpM * 32 + (lane & 7) + ((lane >> 3) & 1) * 8) * ROWB
                   + ((lane >> 4) & 1) * 16);
    const uint32_t b_lmoff =
        (uint32_t)((warpN * WN + (lane & 7) + ((lane >> 4) & 1) * 8) * ROWB
                   + ((lane >> 3) & 1) * 16);

    float acc[2][NTPW][4];
    #pragma unroll
    for (int i = 0; i < 2; i++)
        #pragma unroll
        for (int j = 0; j < NTPW; j++)
            #pragma unroll
            for (int r = 0; r < 4; r++) acc[i][j][r] = 0.f;

    ISSUE(0); CP_COMMIT();
    ISSUE(1); CP_COMMIT();

    for (int t = 0; t < nk; t++) {
        CP_WAIT1();
        __syncthreads();
        if (t + 2 < nk) { ISSUE(t + 2); }
        CP_COMMIT();

        uint32_t as = sb + (t % 3) * STAGE;
        uint32_t bs = as + A_TILE;
        #pragma unroll
        for (int ks = 0; ks < 2; ks++) {
            uint32_t af[2][4];
            uint32_t bf[NTPW][2];
            #pragma unroll
            for (int mt = 0; mt < 2; mt++)
                ldsm4(af[mt], as + a_lmoff + mt * (16 * ROWB) + ks * 32);
            #pragma unroll
            for (int ng = 0; ng < NGRP; ng++) {
                uint32_t r4[4];
                ldsm4(r4, bs + b_lmoff + ng * (16 * ROWB) + ks * 32);
                bf[2*ng][0] = r4[0]; bf[2*ng][1] = r4[1];
                bf[2*ng+1][0] = r4[2]; bf[2*ng+1][1] = r4[3];
            }
            #pragma unroll
            for (int mt = 0; mt < 2; mt++)
                #pragma unroll
                for (int nt = 0; nt < NTPW; nt++)
                    mma_tf32(acc[mt][nt], af[mt], bf[nt]);
        }
        __syncthreads();
    }
    #undef ISSUE

    // epilogue (fragment mapping verified in R2)
    #pragma unroll
    for (int mt = 0; mt < 2; mt++) {
        int row0 = m0 + warpM * 32 + mt * 16 + (lane >> 2);
        #pragma unroll
        for (int nt = 0; nt < NTPW; nt++) {
            int col = n0 + warpN * WN + nt * 8 + (lane & 3) * 2;
            float b0 = 0.f, b1 = 0.f;
            if (BIAS) {
                float2 bb = *reinterpret_cast<const float2*>(bias + col);
                b0 = bb.x; b1 = bb.y;
            }
            #pragma unroll
            for (int rr = 0; rr < 2; rr++) {
                int row = row0 + rr * 8;
                float v0 = acc[mt][nt][rr * 2 + 0] * alpha + b0;
                float v1 = acc[mt][nt][rr * 2 + 1] * alpha + b1;
                if (RELU) { v0 = fmaxf(v0, 0.f); v1 = fmaxf(v1, 0.f); }
                if (RES) {
                    float2 rv = *reinterpret_cast<const float2*>(
                        res + (ll)row * ldc + col);
                    v0 += rv.x; v1 += rv.y;
                }
                if (MASK) {
                    if (col     > row) v0 = -INFINITY;
                    if (col + 1 > row) v1 = -INFINITY;
                }
                if (CVT) { v0 = cvtf32(v0); v1 = cvtf32(v1); }
                if (CTRANS) {
                    Cp[(ll)col * ldc + row] = v0;
                    Cp[(ll)(col + 1) * ldc + row] = v1;
                } else {
                    *reinterpret_cast<float2*>(Cp + (ll)row * ldc + col) =
                        make_float2(v0, v1);
                }
            }
        }
    }
}

// ---------------------------------------------------------------------------
// Column softmax (query-axis), coalesced; rounds output to tf32
// ---------------------------------------------------------------------------
__global__ __launch_bounds__(256)
void softmax_col_kernel(float* __restrict__ S)
{
    const int z  = blockIdx.y;
    const int j0 = blockIdx.x * 256;
    const int j  = j0 + threadIdx.x;
    float* Sz = S + (ll)z * Tq * Tq;

    float m = -INFINITY, s = 0.f;
    for (int i = j0; i < Tq; i++) {
        float v = Sz[(ll)i * Tq + j];
        if (i >= j) {
            if (v > m) { s = s * __expf(m - v) + 1.f; m = v; }
            else       { s += __expf(v - m); }
        }
    }
    float inv = 1.0f / s;
    int i0 = (j >> 7) << 7;
    for (int i = i0; i < Tq; i++) {
        ll idx = (ll)i * Tq + j;
        Sz[idx] = cvtf32(__expf(Sz[idx] - m) * inv);
    }
}

// ---------------------------------------------------------------------------
// Launch sequence
// ---------------------------------------------------------------------------
extern "C" void kernel_launch(void* const* d_in, const int* in_sizes, int n_in,
                              void* d_out, int out_size)
{
    const float* x     = (const float*)d_in[0];
    const float* ln1_w = (const float*)d_in[1];
    const float* Wq    = (const float*)d_in[2];
    const float* bq    = (const float*)d_in[3];
    const float* Wk    = (const float*)d_in[4];
    const float* bk    = (const float*)d_in[5];
    const float* Wv    = (const float*)d_in[6];
    const float* bv    = (const float*)d_in[7];
    const float* Wo    = (const float*)d_in[8];
    const float* bo    = (const float*)d_in[9];
    const float* ln2_w = (const float*)d_in[10];
    const float* W1    = (const float*)d_in[11];
    const float* b1    = (const float*)d_in[12];
    const float* W2    = (const float*)d_in[13];
    const float* b2    = (const float*)d_in[14];
    float* out = (float*)d_out;

    #define GETP(sym, var) void* var##_; cudaGetSymbolAddress(&var##_, sym); \
                           float* var = (float*)var##_;
    GETP(g_h, ph)  GETP(g_q, pq)  GETP(g_k, pk)  GETP(g_vt, pvt)
    GETP(g_S, pS)  GETP(g_att, patt)  GETP(g_x1, px1)  GETP(g_ff, pff)
    GETP(g_wqt, pwqt)  GETP(g_wkt, pwkt)  GETP(g_wvt, pwvt)
    GETP(g_wot, pwot)  GETP(g_w1t, pw1t)  GETP(g_w2t, pw2t)
    #undef GETP

    const int SM128 = 3 * (10240 + 10240);   // 61440
    const int SM64  = 3 * (10240 + 5120);    // 46080

    auto kQK  = mma_gemm<128,true ,false,false,false,false,false,true >;
    auto kV   = mma_gemm<128,true ,false,false,false,false,true ,true >;
    auto kSc  = mma_gemm<128,false,false,false,false,true ,false,false>;
    auto kAV  = mma_gemm<64 ,false,false,false,true ,false,false,true >;
    auto kBR  = mma_gemm<128,true ,false,true ,false,false,false,false>;
    auto kFF1 = mma_gemm<128,true ,true ,false,false,false,false,true >;
    cudaFuncSetAttribute(kQK,  cudaFuncAttributeMaxDynamicSharedMemorySize, SM128);
    cudaFuncSetAttribute(kV,   cudaFuncAttributeMaxDynamicSharedMemorySize, SM128);
    cudaFuncSetAttribute(kSc,  cudaFuncAttributeMaxDynamicSharedMemorySize, SM128);
    cudaFuncSetAttribute(kAV,  cudaFuncAttributeMaxDynamicSharedMemorySize, SM64);
    cudaFuncSetAttribute(kBR,  cudaFuncAttributeMaxDynamicSharedMemorySize, SM128);
    cudaFuncSetAttribute(kFF1, cudaFuncAttributeMaxDynamicSharedMemorySize, SM128);

    // 0) weight transposes (tf32-rounded)
    transpose_kernel<<<dim3(2, 32, Hq), 256>>>(Wq, (ll)Cq*HSq, pwqt, (ll)HSq*Cq, HSq, Cq);
    transpose_kernel<<<dim3(2, 32, Hq), 256>>>(Wk, (ll)Cq*HSq, pwkt, (ll)HSq*Cq, HSq, Cq);
    transpose_kernel<<<dim3(2, 32, Hq), 256>>>(Wv, (ll)Cq*HSq, pwvt, (ll)HSq*Cq, HSq, Cq);
    transpose_kernel<<<dim3(32, 32, 1), 256>>>(Wo, 0, pwot, 0, Cq, Cq);
    transpose_kernel<<<dim3(128, 32, 1), 256>>>(W1, 0, pw1t, 0, FFq, Cq);
    transpose_kernel<<<dim3(32, 128, 1), 256>>>(W2, 0, pw2t, 0, Cq, FFq);

    // 1) LN1
    layernorm_kernel<<<BTq, 256>>>(x, ln1_w, ph);

    // 2) Q,K,V projections: [4096,1024] @ [1024,1024]^T
    {
        dim3 grid(Cq / 128, BTq / 128, 1);
        kQK<<<grid, 256, SM128>>>(ph, 0, 0, pwqt, 0, 0, bq, nullptr,
                                  pq, 0, 0, 1, Cq, Cq, Cq, Cq, 1.0f);
        kQK<<<grid, 256, SM128>>>(ph, 0, 0, pwkt, 0, 0, bk, nullptr,
                                  pk, 0, 0, 1, Cq, Cq, Cq, Cq, 1.0f);
        kV <<<grid, 256, SM128>>>(ph, 0, 0, pwvt, 0, 0, bv, nullptr,
                                  pvt, 0, 0, 1, Cq, Cq, Cq, BTq, 1.0f);
    }

    // 3) Scores: per (h,b): S = 0.125 * Q_h K_h^T (causal)
    {
        dim3 grid(Tq / 128, Tq / 128, Hq * Bq);   // z1=h, z2=b
        kSc<<<grid, 256, SM128>>>(
            pq, (ll)HSq, (ll)Tq * Cq,
            pk, (ll)HSq, (ll)Tq * Cq,
            nullptr, nullptr,
            pS, (ll)Bq * Tq * Tq, (ll)Tq * Tq,
            Bq, HSq, Cq, Cq, Tq, 0.125f);
    }

    // 4) Column softmax (query axis)
    {
        dim3 grid(Tq / 256, Hq * Bq);
        softmax_col_kernel<<<grid, 256>>>(pS);
    }

    // 5) att = W @ V (causal-K), scatter into [B*T][H*HS]
    {
        dim3 grid(1, Tq / 128, Hq * Bq);          // z1=h, z2=b
        kAV<<<grid, 256, SM64>>>(
            pS, (ll)Bq * Tq * Tq, (ll)Tq * Tq,
            pvt, (ll)HSq * BTq, (ll)Tq,
            nullptr, nullptr,
            patt, (ll)HSq, (ll)Tq * Cq,
            Bq, Tq, Tq, BTq, Cq, 1.0f);
    }

    // 6) x1 = x + att @ Wo + bo   (fp32 output)
    {
        dim3 grid(Cq / 128, BTq / 128, 1);
        kBR<<<grid, 256, SM128>>>(patt, 0, 0, pwot, 0, 0, bo, x,
                                  px1, 0, 0, 1, Cq, Cq, Cq, Cq, 1.0f);
    }

    // 7) LN2
    layernorm_kernel<<<BTq, 256>>>(px1, ln2_w, ph);

    // 8) FF1: relu(h2 @ W1 + b1)
    {
        dim3 grid(FFq / 128, BTq / 128, 1);
        kFF1<<<grid, 256, SM128>>>(ph, 0, 0, pw1t, 0, 0, b1, nullptr,
                                   pff, 0, 0, 1, Cq, Cq, Cq, FFq, 1.0f);
    }

    // 9) out = x1 + ff @ W2 + b2
    {
        dim3 grid(Cq / 128, BTq / 128, 1);
        kBR<<<grid, 256, SM128>>>(pff, 0, 0, pw2t, 0, 0, b2, px1,
                                  out, 0, 0, 1, FFq, FFq, FFq, Cq, 1.0f);
    }
}

// round 5
// speedup vs baseline: 3.8318x; 2.2238x over previous
#include <cuda_runtime.h>
#include <cuda_bf16.h>
#include <math.h>
#include <stdint.h>

#define Bq   2
#define Tq   2048
#define Cq   1024
#define Hq   16
#define HSq  64
#define FFq  4096
#define BTq  (Bq*Tq)          // 4096
#define EPSq 1e-5f

typedef long long ll;

// ---------------------------------------------------------------------------
// Scratch (device globals — allocation-free)
// ---------------------------------------------------------------------------
__device__ float g_h  [(size_t)BTq*Cq];
__device__ float g_q  [(size_t)BTq*Cq];               // [B*T][H*HS]
__device__ float g_k  [(size_t)BTq*Cq];
__device__ float g_vt [(size_t)Cq*BTq];               // [H*HS][B*T]
__device__ float g_S  [(size_t)Hq*Bq*Tq*Tq];          // [H][B][T][T] raw scores
__device__ float2 g_part [(size_t)Hq*Bq*16*Tq];       // partial (m,s)
__device__ float2 g_stats[(size_t)Hq*Bq*Tq];          // (m, 1/s) per column
__device__ float g_att[(size_t)BTq*Cq];
__device__ float g_x1 [(size_t)BTq*Cq];
__device__ float g_ff [(size_t)BTq*FFq];
__device__ float g_wqt[(size_t)Cq*Cq];                // [H*HS][C]
__device__ float g_wkt[(size_t)Cq*Cq];
__device__ float g_wvt[(size_t)Cq*Cq];
__device__ float g_wot[(size_t)Cq*Cq];                // [C][H*HS]
__device__ float g_w1t[(size_t)FFq*Cq];               // [FF][C]
__device__ float g_w2t[(size_t)Cq*FFq];               // [C][FF]

// ---------------------------------------------------------------------------
// helpers
// ---------------------------------------------------------------------------
__device__ __forceinline__ float cvtf32(float f) {
    uint32_t u;
    asm("cvt.rna.tf32.f32 %0, %1;" : "=r"(u) : "f"(f));
    return __uint_as_float(u);
}
__device__ __forceinline__ uint32_t smem_u32(const void* p) {
    uint32_t a;
    asm("{ .reg .u64 t; cvta.to.shared.u64 t, %1; cvt.u32.u64 %0, t; }"
        : "=r"(a) : "l"(p));
    return a;
}
__device__ __forceinline__ void cpasync16(uint32_t dst, const void* src) {
    asm volatile("cp.async.cg.shared.global [%0], [%1], 16;"
                 :: "r"(dst), "l"(src));
}
#define CP_COMMIT() asm volatile("cp.async.commit_group;" ::: "memory")
#define CP_WAIT1()  asm volatile("cp.async.wait_group 1;" ::: "memory")

__device__ __forceinline__ void ldsm4(uint32_t* r, uint32_t a) {
    asm volatile("ldmatrix.sync.aligned.m8n8.x4.shared.b16 {%0,%1,%2,%3}, [%4];"
        : "=r"(r[0]), "=r"(r[1]), "=r"(r[2]), "=r"(r[3]) : "r"(a));
}
__device__ __forceinline__ void mma_tf32(float* c, const uint32_t* a, const uint32_t* b) {
    asm volatile(
        "mma.sync.aligned.m16n8k8.row.col.f32.tf32.tf32.f32 "
        "{%0,%1,%2,%3},{%4,%5,%6,%7},{%8,%9},{%0,%1,%2,%3};"
        : "+f"(c[0]), "+f"(c[1]), "+f"(c[2]), "+f"(c[3])
        : "r"(a[0]), "r"(a[1]), "r"(a[2]), "r"(a[3]), "r"(b[0]), "r"(b[1]));
}

// ---------------------------------------------------------------------------
// LayerNorm (tf32-rounds output)
// ---------------------------------------------------------------------------
__global__ __launch_bounds__(256)
void layernorm_kernel(const float* __restrict__ x, const float* __restrict__ w,
                      float* __restrict__ out)
{
    ll r = blockIdx.x;
    int t = threadIdx.x;
    const float4* xr = reinterpret_cast<const float4*>(x + r * Cq);
    float4 v = xr[t];
    float sum = v.x + v.y + v.z + v.w;
    float sq  = v.x*v.x + v.y*v.y + v.z*v.z + v.w*v.w;
    #pragma unroll
    for (int o = 16; o; o >>= 1) {
        sum += __shfl_xor_sync(0xffffffffu, sum, o);
        sq  += __shfl_xor_sync(0xffffffffu, sq,  o);
    }
    __shared__ float s1[8], s2[8];
    __shared__ float mu_s, rstd_s;
    int wid = t >> 5, lane = t & 31;
    if (lane == 0) { s1[wid] = sum; s2[wid] = sq; }
    __syncthreads();
    if (t == 0) {
        float S = 0.f, Q = 0.f;
        #pragma unroll
        for (int i = 0; i < 8; i++) { S += s1[i]; Q += s2[i]; }
        float mu  = S * (1.0f / Cq);
        float var = Q * (1.0f / Cq) - mu * mu;
        mu_s = mu; rstd_s = rsqrtf(var + EPSq);
    }
    __syncthreads();
    float mu = mu_s, rstd = rstd_s;
    float4 ww = reinterpret_cast<const float4*>(w)[t];
    float4 o;
    o.x = cvtf32((v.x - mu) * rstd * ww.x);
    o.y = cvtf32((v.y - mu) * rstd * ww.y);
    o.z = cvtf32((v.z - mu) * rstd * ww.z);
    o.w = cvtf32((v.w - mu) * rstd * ww.w);
    reinterpret_cast<float4*>(out + r * Cq)[t] = o;
}

// ---------------------------------------------------------------------------
// Batched transpose (tf32-rounds output)
// ---------------------------------------------------------------------------
__global__ __launch_bounds__(256)
void transpose_kernel(const float* __restrict__ src, ll s_src,
                      float* __restrict__ dst, ll s_dst,
                      int lds, int ldd)
{
    __shared__ float tile[32][33];
    const float* sp = src + (ll)blockIdx.z * s_src;
    float*       dp = dst + (ll)blockIdx.z * s_dst;
    int cc0 = blockIdx.x * 32;
    int r0  = blockIdx.y * 32;
    int tx = threadIdx.x & 31, ty = threadIdx.x >> 5;
    #pragma unroll
    for (int p = 0; p < 4; p++)
        tile[ty + p * 8][tx] = sp[(ll)(r0 + ty + p * 8) * lds + cc0 + tx];
    __syncthreads();
    #pragma unroll
    for (int p = 0; p < 4; p++)
        dp[(ll)(cc0 + ty + p * 8) * ldd + r0 + tx] = cvtf32(tile[tx][ty + p * 8]);
}

// ---------------------------------------------------------------------------
// mma.sync tf32 GEMM, cp.async 3-stage + ldmatrix (same as R4, verified)
// ---------------------------------------------------------------------------
template<int BN, bool BIAS, bool RELU, bool RES, bool CAUSAL_K, bool MASK,
         bool CTRANS, bool CVT>
__global__ __launch_bounds__(256)
void mma_gemm(const float* __restrict__ A, ll sA1, ll sA2,
              const float* __restrict__ Bm, ll sB1, ll sB2,
              const float* __restrict__ bias,
              const float* __restrict__ res,
              float* __restrict__ C, ll sC1, ll sC2,
              int Z2, int K, int lda, int ldb, int ldc, float alpha)
{
    constexpr int BM   = 128;
    constexpr int ROWB = 80;
    constexpr int A_TILE = BM * ROWB;
    constexpr int B_TILE = BN * ROWB;
    constexpr int STAGE  = A_TILE + B_TILE;
    constexpr int NTPW = BN / 16;
    constexpr int NGRP = NTPW / 2;
    constexpr int WN   = BN / 2;

    extern __shared__ __align__(16) char dsm[];
    const uint32_t sb = smem_u32(dsm);

    const int tid  = threadIdx.x;
    const int lane = tid & 31;
    const int wid  = tid >> 5;
    const int warpM = wid & 3;
    const int warpN = wid >> 2;

    const int z  = blockIdx.z;
    const int z1 = z / Z2, z2 = z - z1 * Z2;
    const int m0 = blockIdx.y * BM;
    const int n0 = blockIdx.x * BN;
    if (MASK && n0 > m0) return;

    const float* Ap = A  + z1 * sA1 + z2 * sA2;
    const float* Bp = Bm + z1 * sB1 + z2 * sB2;
    float*       Cp = C  + z1 * sC1 + z2 * sC2;

    const int Keff = CAUSAL_K ? min(K, m0 + BM) : K;
    const int nk = Keff >> 4;

    const int lr = tid >> 2;
    const int lk = tid & 3;
    const float* a_g = Ap + (ll)(m0 + lr) * lda + lk * 4;
    const float* b_g = Bp + (ll)(n0 + lr) * ldb + lk * 4;
    const uint32_t a_off = (uint32_t)(lr * ROWB + lk * 16);
    const uint32_t b_off = a_off;

    #define ISSUE(t)                                                          \
    {                                                                         \
        int k0 = (t) << 4;                                                    \
        uint32_t as = sb + ((t) % 3) * STAGE;                                 \
        uint32_t bs = as + A_TILE;                                            \
        cpasync16(as + a_off, a_g + k0);                                      \
        cpasync16(as + a_off + 64 * ROWB, a_g + k0 + 64 * (ll)lda);           \
        cpasync16(bs + b_off, b_g + k0);                                      \
        if (BN == 128)                                                        \
            cpasync16(bs + b_off + 64 * ROWB, b_g + k0 + 64 * (ll)ldb);       \
    }

    const uint32_t a_lmoff =
        (uint32_t)((warpM * 32 + (lane & 7) + ((lane >> 3) & 1) * 8) * ROWB
                   + ((lane >> 4) & 1) * 16);
    const uint32_t b_lmoff =
        (uint32_t)((warpN * WN + (lane & 7) + ((lane >> 4) & 1) * 8) * ROWB
                   + ((lane >> 3) & 1) * 16);

    float acc[2][NTPW][4];
    #pragma unroll
    for (int i = 0; i < 2; i++)
        #pragma unroll
        for (int j = 0; j < NTPW; j++)
            #pragma unroll
            for (int r = 0; r < 4; r++) acc[i][j][r] = 0.f;

    ISSUE(0); CP_COMMIT();
    ISSUE(1); CP_COMMIT();

    for (int t = 0; t < nk; t++) {
        CP_WAIT1();
        __syncthreads();
        if (t + 2 < nk) { ISSUE(t + 2); }
        CP_COMMIT();

        uint32_t as = sb + (t % 3) * STAGE;
        uint32_t bs = as + A_TILE;
        #pragma unroll
        for (int ks = 0; ks < 2; ks++) {
            uint32_t af[2][4];
            uint32_t bf[NTPW][2];
            #pragma unroll
            for (int mt = 0; mt < 2; mt++)
                ldsm4(af[mt], as + a_lmoff + mt * (16 * ROWB) + ks * 32);
            #pragma unroll
            for (int ng = 0; ng < NGRP; ng++) {
                uint32_t r4[4];
                ldsm4(r4, bs + b_lmoff + ng * (16 * ROWB) + ks * 32);
                bf[2*ng][0] = r4[0]; bf[2*ng][1] = r4[1];
                bf[2*ng+1][0] = r4[2]; bf[2*ng+1][1] = r4[3];
            }
            #pragma unroll
            for (int mt = 0; mt < 2; mt++)
                #pragma unroll
                for (int nt = 0; nt < NTPW; nt++)
                    mma_tf32(acc[mt][nt], af[mt], bf[nt]);
        }
        __syncthreads();
    }
    #undef ISSUE

    #pragma unroll
    for (int mt = 0; mt < 2; mt++) {
        int row0 = m0 + warpM * 32 + mt * 16 + (lane >> 2);
        #pragma unroll
        for (int nt = 0; nt < NTPW; nt++) {
            int col = n0 + warpN * WN + nt * 8 + (lane & 3) * 2;
            float b0 = 0.f, b1 = 0.f;
            if (BIAS) {
                float2 bb = *reinterpret_cast<const float2*>(bias + col);
                b0 = bb.x; b1 = bb.y;
            }
            #pragma unroll
            for (int rr = 0; rr < 2; rr++) {
                int row = row0 + rr * 8;
                float v0 = acc[mt][nt][rr * 2 + 0] * alpha + b0;
                float v1 = acc[mt][nt][rr * 2 + 1] * alpha + b1;
                if (RELU) { v0 = fmaxf(v0, 0.f); v1 = fmaxf(v1, 0.f); }
                if (RES) {
                    float2 rv = *reinterpret_cast<const float2*>(
                        res + (ll)row * ldc + col);
                    v0 += rv.x; v1 += rv.y;
                }
                if (MASK) {
                    if (col     > row) v0 = -INFINITY;
                    if (col + 1 > row) v1 = -INFINITY;
                }
                if (CVT) { v0 = cvtf32(v0); v1 = cvtf32(v1); }
                if (CTRANS) {
                    Cp[(ll)col * ldc + row] = v0;
                    Cp[(ll)(col + 1) * ldc + row] = v1;
                } else {
                    *reinterpret_cast<float2*>(Cp + (ll)row * ldc + col) =
                        make_float2(v0, v1);
                }
            }
        }
    }
}

// ---------------------------------------------------------------------------
// Column-softmax stats, stage 1: per-(z, 128-row band, column) online (m,s)
// ---------------------------------------------------------------------------
__global__ __launch_bounds__(256)
void stats_partial_kernel(const float* __restrict__ S, float2* __restrict__ part)
{
    const int z  = blockIdx.z;
    const int ib = blockIdx.y;
    const int j  = blockIdx.x * 256 + threadIdx.x;
    float2 out;
    if (ib * 128 + 127 < blockIdx.x * 256) {
        out = make_float2(-INFINITY, 0.f);       // band fully above diagonal
    } else {
        const float* Sz = S + (ll)z * Tq * Tq;
        float m = -INFINITY, s = 0.f;
        const int i0 = ib * 128;
        #pragma unroll 4
        for (int r = 0; r < 128; r++) {
            int i = i0 + r;
            float v = Sz[(ll)i * Tq + j];
            if (i >= j) {
                if (v > m) { s = s * __expf(m - v) + 1.f; m = v; }
                else       { s += __expf(v - m); }
            }
        }
        out = make_float2(m, s);
    }
    part[((ll)z * 16 + ib) * Tq + j] = out;
}

// stage 2: combine 16 partials -> (m, 1/s)
__global__ __launch_bounds__(256)
void stats_combine_kernel(const float2* __restrict__ part,
                          float2* __restrict__ stats)
{
    const int z = blockIdx.y;
    const int j = blockIdx.x * 256 + threadIdx.x;
    float m = -INFINITY, s = 0.f;
    #pragma unroll
    for (int p = 0; p < 16; p++) {
        float2 pr = part[((ll)z * 16 + p) * Tq + j];
        if (pr.y != 0.f) {
            if (pr.x > m) { s = s * __expf(m - pr.x) + pr.y; m = pr.x; }
            else          { s += pr.y * __expf(pr.x - m); }
        }
    }
    stats[(ll)z * Tq + j] = make_float2(m, 1.0f / s);
}

// ---------------------------------------------------------------------------
// Fused attV: att = softmaxW @ V with on-the-fly exp transform of S tiles.
// A = S[z] [T][T] (row i, col j=k), stats (m,1/s) per k.  B = V^T (k-contig).
// BM=128, BN=64, BK=16, causal-K.  3-stage: A via LDG+transform+STS, B cp.async.
// ---------------------------------------------------------------------------
__global__ __launch_bounds__(256)
void attv_kernel(const float* __restrict__ S, ll sA1, ll sA2,
                 const float2* __restrict__ stats, ll sS1,
                 const float* __restrict__ Vt, ll sB1, ll sB2,
                 float* __restrict__ C, ll sC1, ll sC2,
                 int Z2)
{
    constexpr int ROWB = 80;
    constexpr int A_TILE = 128 * ROWB;      // 10240
    constexpr int B_TILE = 64 * ROWB;       // 5120
    constexpr int STAGE  = A_TILE + B_TILE;
    constexpr int NTPW = 4, NGRP = 2, WN = 32;

    extern __shared__ __align__(16) char dsm[];
    const uint32_t sb = smem_u32(dsm);

    const int tid  = threadIdx.x;
    const int lane = tid & 31;
    const int wid  = tid >> 5;
    const int warpM = wid & 3;
    const int warpN = wid >> 2;

    const int z  = blockIdx.z;
    const int z1 = z / Z2, z2 = z - z1 * Z2;
    const int m0 = blockIdx.y * 128;

    const float*  Ap = S  + z1 * sA1 + z2 * sA2;
    const float*  st = reinterpret_cast<const float*>(stats + z1 * sS1 * Bq + z2 * sS1);
    const float*  Bp = Vt + z1 * sB1 + z2 * sB2;
    float*        Cp = C  + z1 * sC1 + z2 * sC2;

    const int nk = (m0 + 128) >> 4;

    const int lr = tid >> 2;
    const int lk = tid & 3;
    const float* a_g = Ap + (ll)(m0 + lr) * Tq + lk * 4;
    const float* b_g = Bp + (ll)lr * BTq + lk * 4;
    const uint32_t ab_off = (uint32_t)(lr * ROWB + lk * 16);

    float4 ra0[2], ra1[2], rs0[2], rs1[2];

    #define LDG_A(t, rsd)                                                     \
    {                                                                         \
        int k0 = (t) << 4;                                                    \
        ra0[rsd] = *reinterpret_cast<const float4*>(a_g + k0);                \
        ra1[rsd] = *reinterpret_cast<const float4*>(a_g + k0 + 64 * (ll)Tq);  \
        rs0[rsd] = *reinterpret_cast<const float4*>(st + 2 * (k0 + lk * 4));  \
        rs1[rsd] = *reinterpret_cast<const float4*>(st + 2 * (k0 + lk * 4) + 4);\
    }
    #define STS_A(t, rsd)                                                     \
    {                                                                         \
        uint32_t as = sb + ((t) % 3) * STAGE;                                 \
        float4 w0, w1;                                                        \
        w0.x = cvtf32(__expf(ra0[rsd].x - rs0[rsd].x) * rs0[rsd].y);          \
        w0.y = cvtf32(__expf(ra0[rsd].y - rs0[rsd].z) * rs0[rsd].w);          \
        w0.z = cvtf32(__expf(ra0[rsd].z - rs1[rsd].x) * rs1[rsd].y);          \
        w0.w = cvtf32(__expf(ra0[rsd].w - rs1[rsd].z) * rs1[rsd].w);          \
        w1.x = cvtf32(__expf(ra1[rsd].x - rs0[rsd].x) * rs0[rsd].y);          \
        w1.y = cvtf32(__expf(ra1[rsd].y - rs0[rsd].z) * rs0[rsd].w);          \
        w1.z = cvtf32(__expf(ra1[rsd].z - rs1[rsd].x) * rs1[rsd].y);          \
        w1.w = cvtf32(__expf(ra1[rsd].w - rs1[rsd].z) * rs1[rsd].w);          \
        *reinterpret_cast<float4*>(dsm + ((as - sb) + ab_off)) = w0;          \
        *reinterpret_cast<float4*>(dsm + ((as - sb) + ab_off + 64 * ROWB)) = w1;\
    }
    #define ISSUE_B(t)                                                        \
    {                                                                         \
        int k0 = (t) << 4;                                                    \
        uint32_t bs = sb + ((t) % 3) * STAGE + A_TILE;                        \
        cpasync16(bs + ab_off, b_g + k0);                                     \
    }

    const uint32_t a_lmoff =
        (uint32_t)((warpM * 32 + (lane & 7) + ((lane >> 3) & 1) * 8) * ROWB
                   + ((lane >> 4) & 1) * 16);
    const uint32_t b_lmoff =
        (uint32_t)((warpN * WN + (lane & 7) + ((lane >> 4) & 1) * 8) * ROWB
                   + ((lane >> 3) & 1) * 16);

    float acc[2][NTPW][4];
    #pragma unroll
    for (int i = 0; i < 2; i++)
        #pragma unroll
        for (int j = 0; j < NTPW; j++)
            #pragma unroll
            for (int r = 0; r < 4; r++) acc[i][j][r] = 0.f;

    LDG_A(0, 0); ISSUE_B(0); CP_COMMIT();
    LDG_A(1, 1); ISSUE_B(1); CP_COMMIT();

    for (int t = 0; t < nk; t++) {
        CP_WAIT1();
        __syncthreads();
        STS_A(t, t & 1);
        if (t + 2 < nk) { LDG_A(t + 2, t & 1); ISSUE_B(t + 2); }
        CP_COMMIT();
        __syncthreads();

        uint32_t as = sb + (t % 3) * STAGE;
        uint32_t bs = as + A_TILE;
        #pragma unroll
        for (int ks = 0; ks < 2; ks++) {
            uint32_t af[2][4];
            uint32_t bf[NTPW][2];
            #pragma unroll
            for (int mt = 0; mt < 2; mt++)
                ldsm4(af[mt], as + a_lmoff + mt * (16 * ROWB) + ks * 32);
            #pragma unroll
            for (int ng = 0; ng < NGRP; ng++) {
                uint32_t r4[4];
                ldsm4(r4, bs + b_lmoff + ng * (16 * ROWB) + ks * 32);
                bf[2*ng][0] = r4[0]; bf[2*ng][1] = r4[1];
                bf[2*ng+1][0] = r4[2]; bf[2*ng+1][1] = r4[3];
            }
            #pragma unroll
            for (int mt = 0; mt < 2; mt++)
                #pragma unroll
                for (int nt = 0; nt < NTPW; nt++)
                    mma_tf32(acc[mt][nt], af[mt], bf[nt]);
        }
    }
    #undef LDG_A
    #undef STS_A
    #undef ISSUE_B
    __syncthreads();

    #pragma unroll
    for (int mt = 0; mt < 2; mt++) {
        int row0 = m0 + warpM * 32 + mt * 16 + (lane >> 2);
        #pragma unroll
        for (int nt = 0; nt < NTPW; nt++) {
            int col = warpN * WN + nt * 8 + (lane & 3) * 2;
            #pragma unroll
            for (int rr = 0; rr < 2; rr++) {
                int row = row0 + rr * 8;
                float v0 = cvtf32(acc[mt][nt][rr * 2 + 0]);
                float v1 = cvtf32(acc[mt][nt][rr * 2 + 1]);
                *reinterpret_cast<float2*>(Cp + (ll)row * Cq + col) =
                    make_float2(v0, v1);
            }
        }
    }
}

// ---------------------------------------------------------------------------
// Launch sequence
// ---------------------------------------------------------------------------
extern "C" void kernel_launch(void* const* d_in, const int* in_sizes, int n_in,
                              void* d_out, int out_size)
{
    const float* x     = (const float*)d_in[0];
    const float* ln1_w = (const float*)d_in[1];
    const float* Wq    = (const float*)d_in[2];
    const float* bq    = (const float*)d_in[3];
    const float* Wk    = (const float*)d_in[4];
    const float* bk    = (const float*)d_in[5];
    const float* Wv    = (const float*)d_in[6];
    const float* bv    = (const float*)d_in[7];
    const float* Wo    = (const float*)d_in[8];
    const float* bo    = (const float*)d_in[9];
    const float* ln2_w = (const float*)d_in[10];
    const float* W1    = (const float*)d_in[11];
    const float* b1    = (const float*)d_in[12];
    const float* W2    = (const float*)d_in[13];
    const float* b2    = (const float*)d_in[14];
    float* out = (float*)d_out;

    #define GETP(sym, var, ty) void* var##_; cudaGetSymbolAddress(&var##_, sym); \
                               ty* var = (ty*)var##_;
    GETP(g_h, ph, float)  GETP(g_q, pq, float)  GETP(g_k, pk, float)
    GETP(g_vt, pvt, float)  GETP(g_S, pS, float)
    GETP(g_part, ppart, float2)  GETP(g_stats, pstats, float2)
    GETP(g_att, patt, float)  GETP(g_x1, px1, float)  GETP(g_ff, pff, float)
    GETP(g_wqt, pwqt, float)  GETP(g_wkt, pwkt, float)  GETP(g_wvt, pwvt, float)
    GETP(g_wot, pwot, float)  GETP(g_w1t, pw1t, float)  GETP(g_w2t, pw2t, float)
    #undef GETP

    const int SM128 = 3 * (10240 + 10240);   // 61440
    const int SMAV  = 3 * (10240 + 5120);    // 46080

    auto kQK  = mma_gemm<128,true ,false,false,false,false,false,true >;
    auto kV   = mma_gemm<128,true ,false,false,false,false,true ,true >;
    auto kSc  = mma_gemm<128,false,false,false,false,true ,false,false>;
    auto kBR  = mma_gemm<128,true ,false,true ,false,false,false,false>;
    auto kFF1 = mma_gemm<128,true ,true ,false,false,false,false,true >;
    cudaFuncSetAttribute(kQK,  cudaFuncAttributeMaxDynamicSharedMemorySize, SM128);
    cudaFuncSetAttribute(kV,   cudaFuncAttributeMaxDynamicSharedMemorySize, SM128);
    cudaFuncSetAttribute(kSc,  cudaFuncAttributeMaxDynamicSharedMemorySize, SM128);
    cudaFuncSetAttribute(kBR,  cudaFuncAttributeMaxDynamicSharedMemorySize, SM128);
    cudaFuncSetAttribute(kFF1, cudaFuncAttributeMaxDynamicSharedMemorySize, SM128);
    cudaFuncSetAttribute(attv_kernel, cudaFuncAttributeMaxDynamicSharedMemorySize, SMAV);

    // 0) weight transposes (tf32-rounded)
    transpose_kernel<<<dim3(2, 32, Hq), 256>>>(Wq, (ll)Cq*HSq, pwqt, (ll)HSq*Cq, HSq, Cq);
    transpose_kernel<<<dim3(2, 32, Hq), 256>>>(Wk, (ll)Cq*HSq, pwkt, (ll)HSq*Cq, HSq, Cq);
    transpose_kernel<<<dim3(2, 32, Hq), 256>>>(Wv, (ll)Cq*HSq, pwvt, (ll)HSq*Cq, HSq, Cq);
    transpose_kernel<<<dim3(32, 32, 1), 256>>>(Wo, 0, pwot, 0, Cq, Cq);
    transpose_kernel<<<dim3(128, 32, 1), 256>>>(W1, 0, pw1t, 0, FFq, Cq);
    transpose_kernel<<<dim3(32, 128, 1), 256>>>(W2, 0, pw2t, 0, Cq, FFq);

    // 1) LN1
    layernorm_kernel<<<BTq, 256>>>(x, ln1_w, ph);

    // 2) Q,K,V projections
    {
        dim3 grid(Cq / 128, BTq / 128, 1);
        kQK<<<grid, 256, SM128>>>(ph, 0, 0, pwqt, 0, 0, bq, nullptr,
                                  pq, 0, 0, 1, Cq, Cq, Cq, Cq, 1.0f);
        kQK<<<grid, 256, SM128>>>(ph, 0, 0, pwkt, 0, 0, bk, nullptr,
                                  pk, 0, 0, 1, Cq, Cq, Cq, Cq, 1.0f);
        kV <<<grid, 256, SM128>>>(ph, 0, 0, pwvt, 0, 0, bv, nullptr,
                                  pvt, 0, 0, 1, Cq, Cq, Cq, BTq, 1.0f);
    }

    // 3) Scores: S = 0.125 * Q K^T (causal, raw fp32)
    {
        dim3 grid(Tq / 128, Tq / 128, Hq * Bq);
        kSc<<<grid, 256, SM128>>>(
            pq, (ll)HSq, (ll)Tq * Cq,
            pk, (ll)HSq, (ll)Tq * Cq,
            nullptr, nullptr,
            pS, (ll)Bq * Tq * Tq, (ll)Tq * Tq,
            Bq, HSq, Cq, Cq, Tq, 0.125f);
    }

    // 4) Column-softmax stats (two-stage)
    {
        dim3 g1(Tq / 256, 16, Hq * Bq);
        stats_partial_kernel<<<g1, 256>>>(pS, ppart);
        dim3 g2(Tq / 256, Hq * Bq);
        stats_combine_kernel<<<g2, 256>>>(ppart, pstats);
    }

    // 5) att = softmaxW @ V (fused exp transform), scatter into [B*T][H*HS]
    {
        dim3 grid(1, Tq / 128, Hq * Bq);   // z1=h, z2=b
        attv_kernel<<<grid, 256, SMAV>>>(
            pS, (ll)Bq * Tq * Tq, (ll)Tq * Tq,
            pstats, (ll)Tq,
            pvt, (ll)HSq * BTq, (ll)Tq,
            patt, (ll)HSq, (ll)Tq * Cq,
            Bq);
    }

    // 6) x1 = x + att @ Wo + bo
    {
        dim3 grid(Cq / 128, BTq / 128, 1);
        kBR<<<grid, 256, SM128>>>(patt, 0, 0, pwot, 0, 0, bo, x,
                                  px1, 0, 0, 1, Cq, Cq, Cq, Cq, 1.0f);
    }

    // 7) LN2
    layernorm_kernel<<<BTq, 256>>>(px1, ln2_w, ph);

    // 8) FF1: relu(h2 @ W1 + b1)
    {
        dim3 grid(FFq / 128, BTq / 128, 1);
        kFF1<<<grid, 256, SM128>>>(ph, 0, 0, pw1t, 0, 0, b1, nullptr,
                                   pff, 0, 0, 1, Cq, Cq, Cq, FFq, 1.0f);
    }

    // 9) out = x1 + ff @ W2 + b2
    {
        dim3 grid(Cq / 128, BTq / 128, 1);
        kBR<<<grid, 256, SM128>>>(pff, 0, 0, pw2t, 0, 0, b2, px1,
                                  out, 0, 0, 1, FFq, FFq, FFq, Cq, 1.0f);
    }
}

// round 6
// speedup vs baseline: 3.9099x; 1.0204x over previous
#include <cuda_runtime.h>
#include <cuda_bf16.h>
#include <math.h>
#include <stdint.h>

#define Bq   2
#define Tq   2048
#define Cq   1024
#define Hq   16
#define HSq  64
#define FFq  4096
#define BTq  (Bq*Tq)          // 4096
#define EPSq 1e-5f

typedef long long ll;

// ---------------------------------------------------------------------------
// Scratch (device globals — allocation-free)
// ---------------------------------------------------------------------------
__device__ float g_h  [(size_t)BTq*Cq];
__device__ float g_qk [(size_t)2*BTq*Cq];             // [2][B*T][H*HS]
__device__ float g_vt [(size_t)Cq*BTq];               // [H*HS][B*T]
__device__ float g_S  [(size_t)Hq*Bq*Tq*Tq];          // [H][B][T][T] raw scores
__device__ float2 g_part [(size_t)Hq*Bq*16*Tq];       // partial (m,s) per band
__device__ float2 g_stats[(size_t)Hq*Bq*Tq];          // (m, 1/s) per column
__device__ float g_att[(size_t)BTq*Cq];
__device__ float g_x1 [(size_t)BTq*Cq];
__device__ float g_ff [(size_t)BTq*FFq];
__device__ float g_wqkt[(size_t)2*Cq*Cq];             // [2][H*HS][C]
__device__ float g_bqk [(size_t)2*Cq];
__device__ float g_wvt[(size_t)Cq*Cq];
__device__ float g_wot[(size_t)Cq*Cq];                // [C][H*HS]
__device__ float g_w1t[(size_t)FFq*Cq];               // [FF][C]
__device__ float g_w2t[(size_t)Cq*FFq];               // [C][FF]

// ---------------------------------------------------------------------------
// helpers
// ---------------------------------------------------------------------------
__device__ __forceinline__ float cvtf32(float f) {
    uint32_t u;
    asm("cvt.rna.tf32.f32 %0, %1;" : "=r"(u) : "f"(f));
    return __uint_as_float(u);
}
__device__ __forceinline__ uint32_t smem_u32(const void* p) {
    uint32_t a;
    asm("{ .reg .u64 t; cvta.to.shared.u64 t, %1; cvt.u32.u64 %0, t; }"
        : "=r"(a) : "l"(p));
    return a;
}
__device__ __forceinline__ void cpasync16(uint32_t dst, const void* src) {
    asm volatile("cp.async.cg.shared.global [%0], [%1], 16;"
                 :: "r"(dst), "l"(src));
}
#define CP_COMMIT() asm volatile("cp.async.commit_group;" ::: "memory")
#define CP_WAIT1()  asm volatile("cp.async.wait_group 1;" ::: "memory")

__device__ __forceinline__ void ldsm4(uint32_t* r, uint32_t a) {
    asm volatile("ldmatrix.sync.aligned.m8n8.x4.shared.b16 {%0,%1,%2,%3}, [%4];"
        : "=r"(r[0]), "=r"(r[1]), "=r"(r[2]), "=r"(r[3]) : "r"(a));
}
__device__ __forceinline__ void mma_tf32(float* c, const uint32_t* a, const uint32_t* b) {
    asm volatile(
        "mma.sync.aligned.m16n8k8.row.col.f32.tf32.tf32.f32 "
        "{%0,%1,%2,%3},{%4,%5,%6,%7},{%8,%9},{%0,%1,%2,%3};"
        : "+f"(c[0]), "+f"(c[1]), "+f"(c[2]), "+f"(c[3])
        : "r"(a[0]), "r"(a[1]), "r"(a[2]), "r"(a[3]), "r"(b[0]), "r"(b[1]));
}

// online softmax helpers (column-softmax stats)
__device__ __forceinline__ void sm_upd(float& m, float& s, float v) {
    if (v > m) { s = s * __expf(m - v) + 1.f; m = v; }
    else if (m > -INFINITY) { s += __expf(v - m); }
}
__device__ __forceinline__ void sm_merge(float& m, float& s, float om, float os) {
    if (os > 0.f) {
        if (om > m) { s = s * __expf(m - om) + os; m = om; }
        else        { s += os * __expf(om - m); }
    }
}

// ---------------------------------------------------------------------------
// LayerNorm (tf32-rounds output)
// ---------------------------------------------------------------------------
__global__ __launch_bounds__(256)
void layernorm_kernel(const float* __restrict__ x, const float* __restrict__ w,
                      float* __restrict__ out)
{
    ll r = blockIdx.x;
    int t = threadIdx.x;
    const float4* xr = reinterpret_cast<const float4*>(x + r * Cq);
    float4 v = xr[t];
    float sum = v.x + v.y + v.z + v.w;
    float sq  = v.x*v.x + v.y*v.y + v.z*v.z + v.w*v.w;
    #pragma unroll
    for (int o = 16; o; o >>= 1) {
        sum += __shfl_xor_sync(0xffffffffu, sum, o);
        sq  += __shfl_xor_sync(0xffffffffu, sq,  o);
    }
    __shared__ float s1[8], s2[8];
    __shared__ float mu_s, rstd_s;
    int wid = t >> 5, lane = t & 31;
    if (lane == 0) { s1[wid] = sum; s2[wid] = sq; }
    __syncthreads();
    if (t == 0) {
        float S = 0.f, Q = 0.f;
        #pragma unroll
        for (int i = 0; i < 8; i++) { S += s1[i]; Q += s2[i]; }
        float mu  = S * (1.0f / Cq);
        float var = Q * (1.0f / Cq) - mu * mu;
        mu_s = mu; rstd_s = rsqrtf(var + EPSq);
    }
    __syncthreads();
    float mu = mu_s, rstd = rstd_s;
    float4 ww = reinterpret_cast<const float4*>(w)[t];
    float4 o;
    o.x = cvtf32((v.x - mu) * rstd * ww.x);
    o.y = cvtf32((v.y - mu) * rstd * ww.y);
    o.z = cvtf32((v.z - mu) * rstd * ww.z);
    o.w = cvtf32((v.w - mu) * rstd * ww.w);
    reinterpret_cast<float4*>(out + r * Cq)[t] = o;
}

// ---------------------------------------------------------------------------
// Batched transpose (tf32-rounds output)
// ---------------------------------------------------------------------------
__global__ __launch_bounds__(256)
void transpose_kernel(const float* __restrict__ src, ll s_src,
                      float* __restrict__ dst, ll s_dst,
                      int lds, int ldd)
{
    __shared__ float tile[32][33];
    const float* sp = src + (ll)blockIdx.z * s_src;
    float*       dp = dst + (ll)blockIdx.z * s_dst;
    int cc0 = blockIdx.x * 32;
    int r0  = blockIdx.y * 32;
    int tx = threadIdx.x & 31, ty = threadIdx.x >> 5;
    #pragma unroll
    for (int p = 0; p < 4; p++)
        tile[ty + p * 8][tx] = sp[(ll)(r0 + ty + p * 8) * lds + cc0 + tx];
    __syncthreads();
    #pragma unroll
    for (int p = 0; p < 4; p++)
        dp[(ll)(cc0 + ty + p * 8) * ldd + r0 + tx] = cvtf32(tile[tx][ty + p * 8]);
}

// concat two bias vectors
__global__ __launch_bounds__(256)
void concat2_kernel(const float* __restrict__ a, const float* __restrict__ b,
                    float* __restrict__ o, int n)
{
    int i = blockIdx.x * 256 + threadIdx.x;
    o[i] = (i < n) ? a[i] : b[i - n];
}

// ---------------------------------------------------------------------------
// mma.sync tf32 GEMM, cp.async 3-stage + ldmatrix.
// STATS: write per-column (m, sumexp) over this CTA's 128-row band to `part`
// (scores kernel only; requires MASK).
// ---------------------------------------------------------------------------
template<int BN, bool BIAS, bool RELU, bool RES, bool CAUSAL_K, bool MASK,
         bool CTRANS, bool CVT, bool STATS>
__global__ __launch_bounds__(256)
void mma_gemm(const float* __restrict__ A, ll sA1, ll sA2,
              const float* __restrict__ Bm, ll sB1, ll sB2,
              const float* __restrict__ bias, ll sb1,
              const float* __restrict__ res,
              float* __restrict__ C, ll sC1, ll sC2,
              float2* __restrict__ part,
              int Z2, int K, int lda, int ldb, int ldc, float alpha)
{
    constexpr int BM   = 128;
    constexpr int ROWB = 80;
    constexpr int A_TILE = BM * ROWB;
    constexpr int B_TILE = BN * ROWB;
    constexpr int STAGE  = A_TILE + B_TILE;
    constexpr int NTPW = BN / 16;
    constexpr int NGRP = NTPW / 2;
    constexpr int WN   = BN / 2;

    extern __shared__ __align__(16) char dsm[];
    const uint32_t sb = smem_u32(dsm);

    const int tid  = threadIdx.x;
    const int lane = tid & 31;
    const int wid  = tid >> 5;
    const int warpM = wid & 3;
    const int warpN = wid >> 2;

    const int z  = blockIdx.z;
    const int z1 = z / Z2, z2 = z - z1 * Z2;
    const int m0 = blockIdx.y * BM;
    const int n0 = blockIdx.x * BN;
    if (MASK && n0 > m0) return;

    const float* Ap = A  + z1 * sA1 + z2 * sA2;
    const float* Bp = Bm + z1 * sB1 + z2 * sB2;
    float*       Cp = C  + z1 * sC1 + z2 * sC2;
    const float* biasp = BIAS ? (bias + z1 * sb1) : nullptr;

    const int Keff = CAUSAL_K ? min(K, m0 + BM) : K;
    const int nk = Keff >> 4;

    const int lr = tid >> 2;
    const int lk = tid & 3;
    const float* a_g = Ap + (ll)(m0 + lr) * lda + lk * 4;
    const float* b_g = Bp + (ll)(n0 + lr) * ldb + lk * 4;
    const uint32_t a_off = (uint32_t)(lr * ROWB + lk * 16);
    const uint32_t b_off = a_off;

    #define ISSUE(t)                                                          \
    {                                                                         \
        int k0 = (t) << 4;                                                    \
        uint32_t as = sb + ((t) % 3) * STAGE;                                 \
        uint32_t bs = as + A_TILE;                                            \
        cpasync16(as + a_off, a_g + k0);                                      \
        cpasync16(as + a_off + 64 * ROWB, a_g + k0 + 64 * (ll)lda);           \
        cpasync16(bs + b_off, b_g + k0);                                      \
        if (BN == 128)                                                        \
            cpasync16(bs + b_off + 64 * ROWB, b_g + k0 + 64 * (ll)ldb);       \
    }

    const uint32_t a_lmoff =
        (uint32_t)((warpM * 32 + (lane & 7) + ((lane >> 3) & 1) * 8) * ROWB
                   + ((lane >> 4) & 1) * 16);
    const uint32_t b_lmoff =
        (uint32_t)((warpN * WN + (lane & 7) + ((lane >> 4) & 1) * 8) * ROWB
                   + ((lane >> 3) & 1) * 16);

    float acc[2][NTPW][4];
    #pragma unroll
    for (int i = 0; i < 2; i++)
        #pragma unroll
        for (int j = 0; j < NTPW; j++)
            #pragma unroll
            for (int r = 0; r < 4; r++) acc[i][j][r] = 0.f;

    ISSUE(0); CP_COMMIT();
    ISSUE(1); CP_COMMIT();

    for (int t = 0; t < nk; t++) {
        CP_WAIT1();
        __syncthreads();
        if (t + 2 < nk) { ISSUE(t + 2); }
        CP_COMMIT();

        uint32_t as = sb + (t % 3) * STAGE;
        uint32_t bs = as + A_TILE;
        #pragma unroll
        for (int ks = 0; ks < 2; ks++) {
            uint32_t af[2][4];
            uint32_t bf[NTPW][2];
            #pragma unroll
            for (int mt = 0; mt < 2; mt++)
                ldsm4(af[mt], as + a_lmoff + mt * (16 * ROWB) + ks * 32);
            #pragma unroll
            for (int ng = 0; ng < NGRP; ng++) {
                uint32_t r4[4];
                ldsm4(r4, bs + b_lmoff + ng * (16 * ROWB) + ks * 32);
                bf[2*ng][0] = r4[0]; bf[2*ng][1] = r4[1];
                bf[2*ng+1][0] = r4[2]; bf[2*ng+1][1] = r4[3];
            }
            #pragma unroll
            for (int mt = 0; mt < 2; mt++)
                #pragma unroll
                for (int nt = 0; nt < NTPW; nt++)
                    mma_tf32(acc[mt][nt], af[mt], bf[nt]);
        }
        __syncthreads();
    }
    #undef ISSUE

    // epilogue (nt-outer keeps stats registers minimal)
    float2* scr = reinterpret_cast<float2*>(dsm);   // stage smem is dead now
    #pragma unroll
    for (int nt = 0; nt < NTPW; nt++) {
        int col = n0 + warpN * WN + nt * 8 + (lane & 3) * 2;
        float b0 = 0.f, b1 = 0.f;
        if (BIAS) {
            float2 bb = *reinterpret_cast<const float2*>(biasp + col);
            b0 = bb.x; b1 = bb.y;
        }
        float cm0 = -INFINITY, cs0 = 0.f, cm1 = -INFINITY, cs1 = 0.f;
        #pragma unroll
        for (int mt = 0; mt < 2; mt++) {
            int row0 = m0 + warpM * 32 + mt * 16 + (lane >> 2);
            #pragma unroll
            for (int rr = 0; rr < 2; rr++) {
                int row = row0 + rr * 8;
                float v0 = acc[mt][nt][rr * 2 + 0] * alpha + b0;
                float v1 = acc[mt][nt][rr * 2 + 1] * alpha + b1;
                if (RELU) { v0 = fmaxf(v0, 0.f); v1 = fmaxf(v1, 0.f); }
                if (RES) {
                    float2 rv = *reinterpret_cast<const float2*>(
                        res + (ll)row * ldc + col);
                    v0 += rv.x; v1 += rv.y;
                }
                if (MASK) {
                    if (col     > row) v0 = -INFINITY;
                    if (col + 1 > row) v1 = -INFINITY;
                }
                if (STATS) { sm_upd(cm0, cs0, v0); sm_upd(cm1, cs1, v1); }
                if (CVT) { v0 = cvtf32(v0); v1 = cvtf32(v1); }
                if (CTRANS) {
                    Cp[(ll)col * ldc + row] = v0;
                    Cp[(ll)(col + 1) * ldc + row] = v1;
                } else {
                    *reinterpret_cast<float2*>(Cp + (ll)row * ldc + col) =
                        make_float2(v0, v1);
                }
            }
        }
        if (STATS) {
            #pragma unroll
            for (int off = 4; off <= 16; off <<= 1) {
                float om0 = __shfl_xor_sync(0xffffffffu, cm0, off);
                float os0 = __shfl_xor_sync(0xffffffffu, cs0, off);
                float om1 = __shfl_xor_sync(0xffffffffu, cm1, off);
                float os1 = __shfl_xor_sync(0xffffffffu, cs1, off);
                sm_merge(cm0, cs0, om0, os0);
                sm_merge(cm1, cs1, om1, os1);
            }
            if ((lane >> 2) == 0) {
                int c = warpN * WN + nt * 8 + lane * 2;
                scr[warpM * BN + c]     = make_float2(cm0, cs0);
                scr[warpM * BN + c + 1] = make_float2(cm1, cs1);
            }
        }
    }
    if (STATS) {
        __syncthreads();
        if (tid < BN) {
            float m = -INFINITY, s = 0.f;
            #pragma unroll
            for (int w = 0; w < 4; w++) {
                float2 p = scr[w * BN + tid];
                sm_merge(m, s, p.x, p.y);
            }
            part[((ll)z * 16 + blockIdx.y) * Tq + n0 + tid] = make_float2(m, s);
        }
    }
}

// combine 128-row band partials -> (m, 1/s); bands above diagonal never written
__global__ __launch_bounds__(256)
void stats_combine_kernel(const float2* __restrict__ part,
                          float2* __restrict__ stats)
{
    const int z = blockIdx.y;
    const int j = blockIdx.x * 256 + threadIdx.x;
    float m = -INFINITY, s = 0.f;
    for (int p = j >> 7; p < 16; p++) {
        float2 pr = part[((ll)z * 16 + p) * Tq + j];
        sm_merge(m, s, pr.x, pr.y);
    }
    stats[(ll)z * Tq + j] = make_float2(m, 1.0f / s);
}

// ---------------------------------------------------------------------------
// Fused attV: att = softmaxW @ V with on-the-fly exp transform of S tiles.
// ---------------------------------------------------------------------------
__global__ __launch_bounds__(256)
void attv_kernel(const float* __restrict__ S, ll sA1, ll sA2,
                 const float2* __restrict__ stats, ll sS1,
                 const float* __restrict__ Vt, ll sB1, ll sB2,
                 float* __restrict__ C, ll sC1, ll sC2,
                 int Z2)
{
    constexpr int ROWB = 80;
    constexpr int A_TILE = 128 * ROWB;
    constexpr int B_TILE = 64 * ROWB;
    constexpr int STAGE  = A_TILE + B_TILE;
    constexpr int NTPW = 4, NGRP = 2, WN = 32;

    extern __shared__ __align__(16) char dsm[];
    const uint32_t sb = smem_u32(dsm);

    const int tid  = threadIdx.x;
    const int lane = tid & 31;
    const int wid  = tid >> 5;
    const int warpM = wid & 3;
    const int warpN = wid >> 2;

    const int z  = blockIdx.z;
    const int z1 = z / Z2, z2 = z - z1 * Z2;
    const int m0 = blockIdx.y * 128;

    const float*  Ap = S  + z1 * sA1 + z2 * sA2;
    const float*  st = reinterpret_cast<const float*>(stats + z1 * sS1 * Bq + z2 * sS1);
    const float*  Bp = Vt + z1 * sB1 + z2 * sB2;
    float*        Cp = C  + z1 * sC1 + z2 * sC2;

    const int nk = (m0 + 128) >> 4;

    const int lr = tid >> 2;
    const int lk = tid & 3;
    const float* a_g = Ap + (ll)(m0 + lr) * Tq + lk * 4;
    const float* b_g = Bp + (ll)lr * BTq + lk * 4;
    const uint32_t ab_off = (uint32_t)(lr * ROWB + lk * 16);

    float4 ra0[2], ra1[2], rs0[2], rs1[2];

    #define LDG_A(t, rsd)                                                     \
    {                                                                         \
        int k0 = (t) << 4;                                                    \
        ra0[rsd] = *reinterpret_cast<const float4*>(a_g + k0);                \
        ra1[rsd] = *reinterpret_cast<const float4*>(a_g + k0 + 64 * (ll)Tq);  \
        rs0[rsd] = *reinterpret_cast<const float4*>(st + 2 * (k0 + lk * 4));  \
        rs1[rsd] = *reinterpret_cast<const float4*>(st + 2 * (k0 + lk * 4) + 4);\
    }
    #define STS_A(t, rsd)                                                     \
    {                                                                         \
        uint32_t as = sb + ((t) % 3) * STAGE;                                 \
        float4 w0, w1;                                                        \
        w0.x = cvtf32(__expf(ra0[rsd].x - rs0[rsd].x) * rs0[rsd].y);          \
        w0.y = cvtf32(__expf(ra0[rsd].y - rs0[rsd].z) * rs0[rsd].w);          \
        w0.z = cvtf32(__expf(ra0[rsd].z - rs1[rsd].x) * rs1[rsd].y);          \
        w0.w = cvtf32(__expf(ra0[rsd].w - rs1[rsd].z) * rs1[rsd].w);          \
        w1.x = cvtf32(__expf(ra1[rsd].x - rs0[rsd].x) * rs0[rsd].y);          \
        w1.y = cvtf32(__expf(ra1[rsd].y - rs0[rsd].z) * rs0[rsd].w);          \
        w1.z = cvtf32(__expf(ra1[rsd].z - rs1[rsd].x) * rs1[rsd].y);          \
        w1.w = cvtf32(__expf(ra1[rsd].w - rs1[rsd].z) * rs1[rsd].w);          \
        *reinterpret_cast<float4*>(dsm + ((as - sb) + ab_off)) = w0;          \
        *reinterpret_cast<float4*>(dsm + ((as - sb) + ab_off + 64 * ROWB)) = w1;\
    }
    #define ISSUE_B(t)                                                        \
    {                                                                         \
        int k0 = (t) << 4;                                                    \
        uint32_t bs = sb + ((t) % 3) * STAGE + A_TILE;                        \
        cpasync16(bs + ab_off, b_g + k0);                                     \
    }

    const uint32_t a_lmoff =
        (uint32_t)((warpM * 32 + (lane & 7) + ((lane >> 3) & 1) * 8) * ROWB
                   + ((lane >> 4) & 1) * 16);
    const uint32_t b_lmoff =
        (uint32_t)((warpN * WN + (lane & 7) + ((lane >> 4) & 1) * 8) * ROWB
                   + ((lane >> 3) & 1) * 16);

    float acc[2][NTPW][4];
    #pragma unroll
    for (int i = 0; i < 2; i++)
        #pragma unroll
        for (int j = 0; j < NTPW; j++)
            #pragma unroll
            for (int r = 0; r < 4; r++) acc[i][j][r] = 0.f;

    LDG_A(0, 0); ISSUE_B(0); CP_COMMIT();
    LDG_A(1, 1); ISSUE_B(1); CP_COMMIT();

    for (int t = 0; t < nk; t++) {
        CP_WAIT1();
        __syncthreads();
        STS_A(t, t & 1);
        if (t + 2 < nk) { LDG_A(t + 2, t & 1); ISSUE_B(t + 2); }
        CP_COMMIT();
        __syncthreads();

        uint32_t as = sb + (t % 3) * STAGE;
        uint32_t bs = as + A_TILE;
        #pragma unroll
        for (int ks = 0; ks < 2; ks++) {
            uint32_t af[2][4];
            uint32_t bf[NTPW][2];
            #pragma unroll
            for (int mt = 0; mt < 2; mt++)
                ldsm4(af[mt], as + a_lmoff + mt * (16 * ROWB) + ks * 32);
            #pragma unroll
            for (int ng = 0; ng < NGRP; ng++) {
                uint32_t r4[4];
                ldsm4(r4, bs + b_lmoff + ng * (16 * ROWB) + ks * 32);
                bf[2*ng][0] = r4[0]; bf[2*ng][1] = r4[1];
                bf[2*ng+1][0] = r4[2]; bf[2*ng+1][1] = r4[3];
            }
            #pragma unroll
            for (int mt = 0; mt < 2; mt++)
                #pragma unroll
                for (int nt = 0; nt < NTPW; nt++)
                    mma_tf32(acc[mt][nt], af[mt], bf[nt]);
        }
    }
    #undef LDG_A
    #undef STS_A
    #undef ISSUE_B
    __syncthreads();

    #pragma unroll
    for (int mt = 0; mt < 2; mt++) {
        int row0 = m0 + warpM * 32 + mt * 16 + (lane >> 2);
        #pragma unroll
        for (int nt = 0; nt < NTPW; nt++) {
            int col = warpN * WN + nt * 8 + (lane & 3) * 2;
            #pragma unroll
            for (int rr = 0; rr < 2; rr++) {
                int row = row0 + rr * 8;
                float v0 = cvtf32(acc[mt][nt][rr * 2 + 0]);
                float v1 = cvtf32(acc[mt][nt][rr * 2 + 1]);
                *reinterpret_cast<float2*>(Cp + (ll)row * Cq + col) =
                    make_float2(v0, v1);
            }
        }
    }
}

// ---------------------------------------------------------------------------
// Launch sequence
// ---------------------------------------------------------------------------
extern "C" void kernel_launch(void* const* d_in, const int* in_sizes, int n_in,
                              void* d_out, int out_size)
{
    const float* x     = (const float*)d_in[0];
    const float* ln1_w = (const float*)d_in[1];
    const float* Wq    = (const float*)d_in[2];
    const float* bq    = (const float*)d_in[3];
    const float* Wk    = (const float*)d_in[4];
    const float* bk    = (const float*)d_in[5];
    const float* Wv    = (const float*)d_in[6];
    const float* bv    = (const float*)d_in[7];
    const float* Wo    = (const float*)d_in[8];
    const float* bo    = (const float*)d_in[9];
    const float* ln2_w = (const float*)d_in[10];
    const float* W1    = (const float*)d_in[11];
    const float* b1    = (const float*)d_in[12];
    const float* W2    = (const float*)d_in[13];
    const float* b2    = (const float*)d_in[14];
    float* out = (float*)d_out;

    #define GETP(sym, var, ty) void* var##_; cudaGetSymbolAddress(&var##_, sym); \
                               ty* var = (ty*)var##_;
    GETP(g_h, ph, float)  GETP(g_qk, pqk, float)  GETP(g_vt, pvt, float)
    GETP(g_S, pS, float)
    GETP(g_part, ppart, float2)  GETP(g_stats, pstats, float2)
    GETP(g_att, patt, float)  GETP(g_x1, px1, float)  GETP(g_ff, pff, float)
    GETP(g_wqkt, pwqkt, float)  GETP(g_bqk, pbqk, float)
    GETP(g_wvt, pwvt, float)
    GETP(g_wot, pwot, float)  GETP(g_w1t, pw1t, float)  GETP(g_w2t, pw2t, float)
    #undef GETP

    const int SM128 = 3 * (10240 + 10240);   // 61440
    const int SMAV  = 3 * (10240 + 5120);    // 46080

    auto kQK  = mma_gemm<128,true ,false,false,false,false,false,true ,false>;
    auto kV   = mma_gemm<128,true ,false,false,false,false,true ,true ,false>;
    auto kSc  = mma_gemm<128,false,false,false,false,true ,false,false,true >;
    auto kBR  = mma_gemm<128,true ,false,true ,false,false,false,false,false>;
    auto kFF1 = mma_gemm<128,true ,true ,false,false,false,false,true ,false>;
    cudaFuncSetAttribute(kQK,  cudaFuncAttributeMaxDynamicSharedMemorySize, SM128);
    cudaFuncSetAttribute(kV,   cudaFuncAttributeMaxDynamicSharedMemorySize, SM128);
    cudaFuncSetAttribute(kSc,  cudaFuncAttributeMaxDynamicSharedMemorySize, SM128);
    cudaFuncSetAttribute(kBR,  cudaFuncAttributeMaxDynamicSharedMemorySize, SM128);
    cudaFuncSetAttribute(kFF1, cudaFuncAttributeMaxDynamicSharedMemorySize, SM128);
    cudaFuncSetAttribute(attv_kernel, cudaFuncAttributeMaxDynamicSharedMemorySize, SMAV);

    // 0) weight transposes (tf32-rounded) + bias concat
    transpose_kernel<<<dim3(2, 32, Hq), 256>>>(Wq, (ll)Cq*HSq, pwqkt, (ll)HSq*Cq, HSq, Cq);
    transpose_kernel<<<dim3(2, 32, Hq), 256>>>(Wk, (ll)Cq*HSq, pwqkt + (ll)Cq*Cq, (ll)HSq*Cq, HSq, Cq);
    transpose_kernel<<<dim3(2, 32, Hq), 256>>>(Wv, (ll)Cq*HSq, pwvt, (ll)HSq*Cq, HSq, Cq);
    transpose_kernel<<<dim3(32, 32, 1), 256>>>(Wo, 0, pwot, 0, Cq, Cq);
    transpose_kernel<<<dim3(128, 32, 1), 256>>>(W1, 0, pw1t, 0, FFq, Cq);
    transpose_kernel<<<dim3(32, 128, 1), 256>>>(W2, 0, pw2t, 0, Cq, FFq);
    concat2_kernel<<<2 * Cq / 256, 256>>>(bq, bk, pbqk, Cq);

    // 1) LN1
    layernorm_kernel<<<BTq, 256>>>(x, ln1_w, ph);

    // 2) Q,K (batched z=2) and V projections
    {
        dim3 gridQK(Cq / 128, BTq / 128, 2);
        kQK<<<gridQK, 256, SM128>>>(ph, 0, 0, pwqkt, (ll)Cq*Cq, 0, pbqk, Cq, nullptr,
                                    pqk, (ll)BTq*Cq, 0, nullptr,
                                    1, Cq, Cq, Cq, Cq, 1.0f);
        dim3 gridV(Cq / 128, BTq / 128, 1);
        kV <<<gridV, 256, SM128>>>(ph, 0, 0, pwvt, 0, 0, bv, 0, nullptr,
                                   pvt, 0, 0, nullptr,
                                   1, Cq, Cq, Cq, BTq, 1.0f);
    }

    // 3) Scores + fused per-band column stats
    {
        dim3 grid(Tq / 128, Tq / 128, Hq * Bq);
        kSc<<<grid, 256, SM128>>>(
            pqk, (ll)HSq, (ll)Tq * Cq,
            pqk + (ll)BTq * Cq, (ll)HSq, (ll)Tq * Cq,
            nullptr, 0, nullptr,
            pS, (ll)Bq * Tq * Tq, (ll)Tq * Tq,
            ppart,
            Bq, HSq, Cq, Cq, Tq, 0.125f);
    }

    // 4) Combine band stats -> (m, 1/s)
    {
        dim3 g2(Tq / 256, Hq * Bq);
        stats_combine_kernel<<<g2, 256>>>(ppart, pstats);
    }

    // 5) att = softmaxW @ V (fused exp transform)
    {
        dim3 grid(1, Tq / 128, Hq * Bq);
        attv_kernel<<<grid, 256, SMAV>>>(
            pS, (ll)Bq * Tq * Tq, (ll)Tq * Tq,
            pstats, (ll)Tq,
            pvt, (ll)HSq * BTq, (ll)Tq,
            patt, (ll)HSq, (ll)Tq * Cq,
            Bq);
    }

    // 6) x1 = x + att @ Wo + bo
    {
        dim3 grid(Cq / 128, BTq / 128, 1);
        kBR<<<grid, 256, SM128>>>(patt, 0, 0, pwot, 0, 0, bo, 0, x,
                                  px1, 0, 0, nullptr, 1, Cq, Cq, Cq, Cq, 1.0f);
    }

    // 7) LN2
    layernorm_kernel<<<BTq, 256>>>(px1, ln2_w, ph);

    // 8) FF1: relu(h2 @ W1 + b1)
    {
        dim3 grid(FFq / 128, BTq / 128, 1);
        kFF1<<<grid, 256, SM128>>>(ph, 0, 0, pw1t, 0, 0, b1, 0, nullptr,
                                   pff, 0, 0, nullptr, 1, Cq, Cq, Cq, FFq, 1.0f);
    }

    // 9) out = x1 + ff @ W2 + b2
    {
        dim3 grid(Cq / 128, BTq / 128, 1);
        kBR<<<grid, 256, SM128>>>(pff, 0, 0, pw2t, 0, 0, b2, 0, px1,
                                  out, 0, 0, nullptr, 1, FFq, FFq, FFq, Cq, 1.0f);
    }
}